// round 11
// baseline (speedup 1.0000x reference)
#include <cuda_runtime.h>
#include <cuda_bf16.h>
#include <cstdint>

// Problem constants
#define DMODEL 1024
#define HEADS  16
#define DK     64
#define BATCH  2
#define SEQ    2048
#define MROWS  (BATCH * SEQ)          // 4096
#define BH     (BATCH * HEADS)        // 32

// ---------------- scratch (static device memory; no allocs) ----------------
__device__ float g_ctx[MROWS * DMODEL];            // [B*S][1024]

__device__ __nv_bfloat16 g_qhi[MROWS * DMODEL], g_qlo[MROWS * DMODEL];
__device__ __nv_bfloat16 g_khi[MROWS * DMODEL], g_klo[MROWS * DMODEL];
__device__ __nv_bfloat16 g_vhi[MROWS * DMODEL], g_vlo[MROWS * DMODEL];
__device__ __nv_bfloat16 g_chi[MROWS * DMODEL], g_clo[MROWS * DMODEL];
__device__ __nv_bfloat16 g_wqhi[DMODEL * DMODEL], g_wqlo[DMODEL * DMODEL];
__device__ __nv_bfloat16 g_wkhi[DMODEL * DMODEL], g_wklo[DMODEL * DMODEL];
__device__ __nv_bfloat16 g_wvhi[DMODEL * DMODEL], g_wvlo[DMODEL * DMODEL];
__device__ __nv_bfloat16 g_wohi[DMODEL * DMODEL], g_wolo[DMODEL * DMODEL];
__device__ __nv_bfloat16 g_qshi[BH * SEQ * DK], g_qslo[BH * SEQ * DK]; // [bh][s][dk]
__device__ __nv_bfloat16 g_kshi[BH * SEQ * DK], g_kslo[BH * SEQ * DK]; // [bh][s][dk]
__device__ __nv_bfloat16 g_vthi[BH * DK * SEQ], g_vtlo[BH * DK * SEQ]; // [bh][dk][s]

// ---------------- helpers ---------------------------------------------------
__device__ __forceinline__ void mma16816(float* c, const uint32_t* a, const uint32_t* b) {
    asm volatile(
        "mma.sync.aligned.m16n8k16.row.col.f32.bf16.bf16.f32 "
        "{%0,%1,%2,%3}, {%4,%5,%6,%7}, {%8,%9}, {%0,%1,%2,%3};"
        : "+f"(c[0]), "+f"(c[1]), "+f"(c[2]), "+f"(c[3])
        : "r"(a[0]), "r"(a[1]), "r"(a[2]), "r"(a[3]), "r"(b[0]), "r"(b[1]));
}
__device__ __forceinline__ void ldsm4(uint32_t* r, uint32_t addr) {
    asm volatile("ldmatrix.sync.aligned.m8n8.x4.shared.b16 {%0,%1,%2,%3}, [%4];"
        : "=r"(r[0]), "=r"(r[1]), "=r"(r[2]), "=r"(r[3]) : "r"(addr));
}
__device__ __forceinline__ uint32_t smem_u32(const void* p) {
    uint32_t a;
    asm("{ .reg .u64 t; cvta.to.shared.u64 t, %1; cvt.u32.u64 %0, t; }"
        : "=r"(a) : "l"(p));
    return a;
}
__device__ __forceinline__ void cpa16(uint32_t dst, const void* src) {
    asm volatile("cp.async.cg.shared.global [%0], [%1], 16;" :: "r"(dst), "l"(src));
}
__device__ __forceinline__ void cpa_commit() {
    asm volatile("cp.async.commit_group;" ::: "memory");
}
template <int N>
__device__ __forceinline__ void cpa_wait() {
    asm volatile("cp.async.wait_group %0;" :: "n"(N) : "memory");
}
__device__ __forceinline__ float ex2f(float x) {
    float y; asm("ex2.approx.ftz.f32 %0, %1;" : "=f"(y) : "f"(x)); return y;
}
__device__ __forceinline__ uint32_t pack_bf2(float a, float b) {
    __nv_bfloat162 t = __floats2bfloat162_rn(a, b);
    return *reinterpret_cast<uint32_t*>(&t);
}
// 64B-row XOR swizzle: 16B chunk index ^= (r>>1)&3.
// Conflict-free for 8-row ldmatrix sets and cp.async warp stores.
__device__ __forceinline__ uint32_t swz64(int r, int byte) {
    return (uint32_t)(r * 64 + ((((byte >> 4) ^ ((r >> 1) & 3)) << 4) | (byte & 15)));
}

// ---------------- split fp32 -> bf16 hi/lo (batched up to 4 tensors) -------
__global__ __launch_bounds__(256) void split_bf16_multi(
    const float4* __restrict__ x0, uint2* __restrict__ h0, uint2* __restrict__ l0,
    const float4* __restrict__ x1, uint2* __restrict__ h1, uint2* __restrict__ l1,
    const float4* __restrict__ x2, uint2* __restrict__ h2, uint2* __restrict__ l2,
    const float4* __restrict__ x3, uint2* __restrict__ h3, uint2* __restrict__ l3,
    int n4)
{
    const int sel = blockIdx.y;
    const float4* x = (sel == 0) ? x0 : (sel == 1) ? x1 : (sel == 2) ? x2 : x3;
    uint2* hi = (sel == 0) ? h0 : (sel == 1) ? h1 : (sel == 2) ? h2 : h3;
    uint2* lo = (sel == 0) ? l0 : (sel == 1) ? l1 : (sel == 2) ? l2 : l3;
    if (x == nullptr) return;

    int i = blockIdx.x * blockDim.x + threadIdx.x;
    if (i >= n4) return;
    float4 v = x[i];
    float f[4] = {v.x, v.y, v.z, v.w};
    unsigned short hb[4], lb[4];
#pragma unroll
    for (int j = 0; j < 4; j++) {
        __nv_bfloat16 h = __float2bfloat16(f[j]);
        float r = f[j] - __bfloat162float(h);
        __nv_bfloat16 l = __float2bfloat16(r);
        hb[j] = __bfloat16_as_ushort(h);
        lb[j] = __bfloat16_as_ushort(l);
    }
    hi[i] = make_uint2((uint32_t)hb[0] | ((uint32_t)hb[1] << 16),
                       (uint32_t)hb[2] | ((uint32_t)hb[3] << 16));
    lo[i] = make_uint2((uint32_t)lb[0] | ((uint32_t)lb[1] << 16),
                       (uint32_t)lb[2] | ((uint32_t)lb[3] << 16));
}

// ---------------- mma.sync bf16 GEMM: Y = (X @ W^T + bias) * scale ---------
// 128x128 tile, warp tile 32(M)x64(N), BK=32 (64B rows, XOR swizzle, no pad).
// 3-stage cp.async pipeline, ONE barrier per chunk, 2 CTAs/SM
// (regs<=128 via __launch_bounds__(256,2); smem 3x32KB=96KB/CTA).
#define TILE_B    (128 * 64)           // 8192 bytes per array
#define GBUF      (4 * TILE_B)         // Ahi|Alo|Bhi|Blo = 32768
#define GEMM_SMEM (3 * GBUF)           // 98304 -> 2 CTAs/SM
#define NCHUNK    32

template <int MODE>
__global__ __launch_bounds__(256, 2) void gemm_mma(
    const __nv_bfloat16* __restrict__ Ahi, const __nv_bfloat16* __restrict__ Alo,
    const __nv_bfloat16* __restrict__ Bhi, const __nv_bfloat16* __restrict__ Blo,
    const float* __restrict__ bias, float scale,
    float* __restrict__ Yf,
    __nv_bfloat16* __restrict__ Yhi, __nv_bfloat16* __restrict__ Ylo)
{
    extern __shared__ __align__(16) char smem_raw[];
    const uint32_t sb = smem_u32(smem_raw);

    const int tid  = threadIdx.x;
    const int wid  = tid >> 5, lane = tid & 31;
    const int wm   = wid & 3;            // 4 warps along M (32 each)
    const int wn   = wid >> 2;           // 2 warps along N (64 each)
    const int qr   = lane >> 2;
    const int qc   = lane & 3;
    const int row0 = blockIdx.y * 128;
    const int col0 = blockIdx.x * 128;

    const int lrow = (lane & 7) + ((lane >> 3) & 1) * 8;
    const int lbyt = (lane >> 4) * 16;

    float acc[2][8][4];                  // warp tile 32x64
#pragma unroll
    for (int a = 0; a < 2; a++)
#pragma unroll
        for (int b = 0; b < 8; b++)
#pragma unroll
            for (int c = 0; c < 4; c++) acc[a][b][c] = 0.f;

    // 2048 x 16B transfers per chunk -> 8 per thread
    auto cpa_chunk = [&](int c, int buf) {
        const uint32_t db = sb + buf * GBUF;
#pragma unroll
        for (int i = 0; i < 8; i++) {
            const int u   = tid + i * 256;
            const int arr = u >> 9;            // 0=Ahi 1=Alo 2=Bhi 3=Blo
            const int r   = (u & 511) >> 2;
            const int ch  = u & 3;
            const __nv_bfloat16* src =
                (arr == 0) ? Ahi : (arr == 1) ? Alo : (arr == 2) ? Bhi : Blo;
            const int grow = ((arr < 2) ? row0 : col0) + r;
            cpa16(db + arr * TILE_B + swz64(r, ch * 16),
                  src + (size_t)grow * DMODEL + c * 32 + ch * 8);
        }
        cpa_commit();
    };

    cpa_chunk(0, 0);
    cpa_chunk(1, 1);

#pragma unroll 1
    for (int c = 0; c < NCHUNK; c++) {
        if (c == NCHUNK - 1) cpa_wait<0>(); else cpa_wait<1>();
        __syncthreads();                  // chunk c visible everywhere
        if (c + 2 < NCHUNK) cpa_chunk(c + 2, (c + 2) % 3);

        const uint32_t bb = sb + (c % 3) * GBUF;
#pragma unroll
        for (int ks = 0; ks < 2; ks++) {
            const int kb = ks * 32 + lbyt;

            uint32_t bhf[8][2], blf[8][2];
#pragma unroll
            for (int half = 0; half < 4; half++) {
                const int br = wn * 64 + half * 16 + lrow;
                const uint32_t so = swz64(br, kb);
                uint32_t th[4], tl[4];
                ldsm4(th, bb + 2 * TILE_B + so);
                ldsm4(tl, bb + 3 * TILE_B + so);
                bhf[half * 2 + 0][0] = th[0]; bhf[half * 2 + 1][0] = th[1];
                bhf[half * 2 + 0][1] = th[2]; bhf[half * 2 + 1][1] = th[3];
                blf[half * 2 + 0][0] = tl[0]; blf[half * 2 + 1][0] = tl[1];
                blf[half * 2 + 0][1] = tl[2]; blf[half * 2 + 1][1] = tl[3];
            }
#pragma unroll
            for (int mt = 0; mt < 2; mt++) {
                const int ar = wm * 32 + mt * 16 + lrow;
                const uint32_t so = swz64(ar, kb);
                uint32_t ah[4], al[4];
                ldsm4(ah, bb + so);
                ldsm4(al, bb + TILE_B + so);
#pragma unroll
                for (int nt = 0; nt < 8; nt++) {
                    mma16816(acc[mt][nt], ah, bhf[nt]);
                    mma16816(acc[mt][nt], ah, blf[nt]);
                    mma16816(acc[mt][nt], al, bhf[nt]);
                }
            }
        }
    }

    // ---- epilogue ----
#pragma unroll
    for (int mt = 0; mt < 2; mt++) {
#pragma unroll
        for (int nt = 0; nt < 8; nt++) {
            const int col = col0 + wn * 64 + nt * 8 + qc * 2;
            float2 bv = *(const float2*)&bias[col];
#pragma unroll
            for (int h = 0; h < 2; h++) {
                const int m = row0 + wm * 32 + mt * 16 + qr + h * 8;
                float v0 = (acc[mt][nt][h * 2 + 0] + bv.x) * scale;
                float v1 = (acc[mt][nt][h * 2 + 1] + bv.y) * scale;
                if (MODE == 0) {
                    float2 r; r.x = v0; r.y = v1;
                    *(float2*)(Yf + (size_t)m * DMODEL + col) = r;
                } else {
                    const int b  = m >> 11, s = m & (SEQ - 1);
                    const int hh = col >> 6, dk = col & 63;
                    __nv_bfloat16 h0 = __float2bfloat16(v0);
                    __nv_bfloat16 h1 = __float2bfloat16(v1);
                    float r0 = v0 - __bfloat162float(h0);
                    float r1 = v1 - __bfloat162float(h1);
                    __nv_bfloat16 l0 = __float2bfloat16(r0);
                    __nv_bfloat16 l1 = __float2bfloat16(r1);
                    if (MODE == 1) {
                        const size_t idx = ((size_t)(b * HEADS + hh) * SEQ + s) * DK + dk;
                        *(uint32_t*)(Yhi + idx) =
                            (uint32_t)__bfloat16_as_ushort(h0) |
                            ((uint32_t)__bfloat16_as_ushort(h1) << 16);
                        *(uint32_t*)(Ylo + idx) =
                            (uint32_t)__bfloat16_as_ushort(l0) |
                            ((uint32_t)__bfloat16_as_ushort(l1) << 16);
                    } else {           // MODE 2: transposed [bh][dk][s]
                        const size_t base = ((size_t)(b * HEADS + hh) * DK + dk) * SEQ + s;
                        Yhi[base]       = h0;  Yhi[base + SEQ] = h1;
                        Ylo[base]       = l0;  Ylo[base + SEQ] = l1;
                    }
                }
            }
        }
    }
}

// ---------------- tensor-core flash attention (unchanged from R10) ----------
#define ATS    144
#define KTILE  (64 * ATS)              // 9216
#define FBUF   (4 * KTILE)             // Khi|Klo|Vthi|Vtlo = 36864
#define FLASH_SMEM (3 * FBUF)          // 110592
#define NT     (SEQ / 64)              // 32

__global__ __launch_bounds__(256) void flash_mma(
    const __nv_bfloat16* __restrict__ Qhi, const __nv_bfloat16* __restrict__ Qlo,
    const __nv_bfloat16* __restrict__ Khi, const __nv_bfloat16* __restrict__ Klo,
    const __nv_bfloat16* __restrict__ Vthi, const __nv_bfloat16* __restrict__ Vtlo,
    float* __restrict__ Ctx)
{
    extern __shared__ __align__(16) char sm[];
    const uint32_t sbf = smem_u32(sm);

    const int tid = threadIdx.x, wid = tid >> 5, lane = tid & 31;
    const int qr = lane >> 2, qc = lane & 3;
    const int bh = blockIdx.y;
    const int s0 = blockIdx.x * 128;
    const int b  = bh >> 4, h = bh & 15;

    // ---- stage Q tile (hi at 0, lo at 2*KTILE), extract A-fragments ----
#pragma unroll
    for (int i = 0; i < 8; i++) {
        int u = tid + i * 256;          // 0..2047
        int arr = u >> 10;              // 0=hi 1=lo
        int idx = u & 1023, r = idx >> 3, ch = idx & 7;
        const __nv_bfloat16* src = arr ? Qlo : Qhi;
        *(float4*)(sm + arr * 2 * KTILE + r * ATS + ch * 16) =
            *(const float4*)(src + ((size_t)bh * SEQ + s0 + r) * DK + ch * 8);
    }
    __syncthreads();
    uint32_t qfh[4][4], qfl[4][4];
    {
        const char* base = sm + (wid * 16 + qr) * ATS;
#pragma unroll
        for (int kt = 0; kt < 4; kt++) {
            const int off = kt * 32 + qc * 4;
            qfh[kt][0] = *(const uint32_t*)(base + off);
            qfh[kt][1] = *(const uint32_t*)(base + 8 * ATS + off);
            qfh[kt][2] = *(const uint32_t*)(base + off + 16);
            qfh[kt][3] = *(const uint32_t*)(base + 8 * ATS + off + 16);
            qfl[kt][0] = *(const uint32_t*)(base + 2 * KTILE + off);
            qfl[kt][1] = *(const uint32_t*)(base + 2 * KTILE + 8 * ATS + off);
            qfl[kt][2] = *(const uint32_t*)(base + 2 * KTILE + off + 16);
            qfl[kt][3] = *(const uint32_t*)(base + 2 * KTILE + 8 * ATS + off + 16);
        }
    }
    __syncthreads();                    // Q fully consumed before buf0 reuse

    float O[8][4];
#pragma unroll
    for (int nt = 0; nt < 8; nt++)
#pragma unroll
        for (int c = 0; c < 4; c++) O[nt][c] = 0.f;
    float m0 = -1e30f, m1 = -1e30f, l0 = 0.f, l1 = 0.f;

    auto cpaKV = [&](int t, int buf) {
        const uint32_t db = sbf + buf * FBUF;
        const int j0 = t * 64;
#pragma unroll
        for (int i = 0; i < 8; i++) {
            int u = tid + i * 256;
            int arr = u >> 9;           // 0=Khi 1=Klo 2=Vthi 3=Vtlo
            int idx = u & 511, r = idx >> 3, ch = idx & 7;
            const __nv_bfloat16* src =
                (arr == 0) ? Khi : (arr == 1) ? Klo : (arr == 2) ? Vthi : Vtlo;
            size_t g = (arr < 2)
                ? (((size_t)bh * SEQ + j0 + r) * DK + ch * 8)
                : (((size_t)bh * DK + r) * SEQ + j0 + ch * 8);
            cpa16(db + arr * KTILE + r * ATS + ch * 16, src + g);
        }
        cpa_commit();
    };

    cpaKV(0, 0);
    cpaKV(1, 1);

#pragma unroll 1
    for (int t = 0; t < NT; t++) {
        if (t == NT - 1) cpa_wait<0>(); else cpa_wait<1>();
        __syncthreads();
        if (t + 2 < NT) cpaKV(t + 2, (t + 2) % 3);
        const char* smb = sm + (t % 3) * FBUF;

        // ---- S = Q K^T (3-product split), base-2 domain ----
        float S[8][4];
#pragma unroll
        for (int nt = 0; nt < 8; nt++)
#pragma unroll
            for (int c = 0; c < 4; c++) S[nt][c] = 0.f;

#pragma unroll
        for (int kt = 0; kt < 4; kt++) {
            const int kb = kt * 32 + qc * 4;
#pragma unroll
            for (int nt = 0; nt < 8; nt++) {
                const char* kp = smb + (nt * 8 + qr) * ATS + kb;
                uint32_t kbh[2], kbl[2];
                kbh[0] = *(const uint32_t*)kp;
                kbh[1] = *(const uint32_t*)(kp + 16);
                kbl[0] = *(const uint32_t*)(kp + KTILE);
                kbl[1] = *(const uint32_t*)(kp + KTILE + 16);
                mma16816(S[nt], qfh[kt], kbh);
                mma16816(S[nt], qfh[kt], kbl);
                mma16816(S[nt], qfl[kt], kbh);
            }
        }

        // ---- online softmax (base 2) ----
        float rx0 = -1e30f, rx1 = -1e30f;
#pragma unroll
        for (int nt = 0; nt < 8; nt++) {
            rx0 = fmaxf(rx0, fmaxf(S[nt][0], S[nt][1]));
            rx1 = fmaxf(rx1, fmaxf(S[nt][2], S[nt][3]));
        }
        rx0 = fmaxf(rx0, __shfl_xor_sync(0xffffffffu, rx0, 1));
        rx0 = fmaxf(rx0, __shfl_xor_sync(0xffffffffu, rx0, 2));
        rx1 = fmaxf(rx1, __shfl_xor_sync(0xffffffffu, rx1, 1));
        rx1 = fmaxf(rx1, __shfl_xor_sync(0xffffffffu, rx1, 2));

        const float mn0 = fmaxf(m0, rx0);
        const float mn1 = fmaxf(m1, rx1);
        const float a0 = ex2f(m0 - mn0);
        const float a1 = ex2f(m1 - mn1);
        m0 = mn0; m1 = mn1;
        l0 *= a0;  l1 *= a1;

#pragma unroll
        for (int nt = 0; nt < 8; nt++) {
            S[nt][0] = ex2f(S[nt][0] - m0);
            S[nt][1] = ex2f(S[nt][1] - m0);
            S[nt][2] = ex2f(S[nt][2] - m1);
            S[nt][3] = ex2f(S[nt][3] - m1);
            l0 += S[nt][0] + S[nt][1];
            l1 += S[nt][2] + S[nt][3];
            O[nt][0] *= a0; O[nt][1] *= a0;
            O[nt][2] *= a1; O[nt][3] *= a1;
        }

        // ---- O += P V (P split hi/lo in registers) ----
#pragma unroll
        for (int kt = 0; kt < 4; kt++) {
            uint32_t ph[4], pl[4];
#pragma unroll
            for (int half = 0; half < 2; half++) {
                const float* sv = S[2 * kt + half];
                __nv_bfloat16 h0 = __float2bfloat16(sv[0]);
                __nv_bfloat16 h1 = __float2bfloat16(sv[1]);
                __nv_bfloat16 h2 = __float2bfloat16(sv[2]);
                __nv_bfloat16 h3 = __float2bfloat16(sv[3]);
                ph[half * 2 + 0] = (uint32_t)__bfloat16_as_ushort(h0) |
                                   ((uint32_t)__bfloat16_as_ushort(h1) << 16);
                ph[half * 2 + 1] = (uint32_t)__bfloat16_as_ushort(h2) |
                                   ((uint32_t)__bfloat16_as_ushort(h3) << 16);
                pl[half * 2 + 0] = pack_bf2(sv[0] - __bfloat162float(h0),
                                            sv[1] - __bfloat162float(h1));
                pl[half * 2 + 1] = pack_bf2(sv[2] - __bfloat162float(h2),
                                            sv[3] - __bfloat162float(h3));
            }
            uint32_t ah[4] = {ph[0], ph[1], ph[2], ph[3]};
            uint32_t al[4] = {pl[0], pl[1], pl[2], pl[3]};

            const int kb = kt * 32 + qc * 4;
#pragma unroll
            for (int nt = 0; nt < 8; nt++) {
                const char* vp = smb + 2 * KTILE + (nt * 8 + qr) * ATS + kb;
                uint32_t vbh[2], vbl[2];
                vbh[0] = *(const uint32_t*)vp;
                vbh[1] = *(const uint32_t*)(vp + 16);
                vbl[0] = *(const uint32_t*)(vp + KTILE);
                vbl[1] = *(const uint32_t*)(vp + KTILE + 16);
                mma16816(O[nt], ah, vbh);
                mma16816(O[nt], ah, vbl);
                mma16816(O[nt], al, vbh);
            }
        }
    }

    // ---- finalize ----
    l0 += __shfl_xor_sync(0xffffffffu, l0, 1);
    l0 += __shfl_xor_sync(0xffffffffu, l0, 2);
    l1 += __shfl_xor_sync(0xffffffffu, l1, 1);
    l1 += __shfl_xor_sync(0xffffffffu, l1, 2);
    const float inv0 = 1.f / l0, inv1 = 1.f / l1;

    const int s = s0 + wid * 16 + qr;
#pragma unroll
    for (int nt = 0; nt < 8; nt++) {
        const int col = h * DK + nt * 8 + qc * 2;
        float2 r0; r0.x = O[nt][0] * inv0; r0.y = O[nt][1] * inv0;
        float2 r1; r1.x = O[nt][2] * inv1; r1.y = O[nt][3] * inv1;
        *(float2*)(Ctx + ((size_t)(b * SEQ + s)     ) * DMODEL + col) = r0;
        *(float2*)(Ctx + ((size_t)(b * SEQ + s + 8) ) * DMODEL + col) = r1;
    }
}

// ---------------- launch ---------------------------------------------------
extern "C" void kernel_launch(void* const* d_in, const int* in_sizes, int n_in,
                              void* d_out, int out_size)
{
    (void)in_sizes; (void)n_in; (void)out_size;
    const float* q    = (const float*)d_in[0];
    const float* k    = (const float*)d_in[1];
    const float* v    = (const float*)d_in[2];
    const float* wq_w = (const float*)d_in[4];
    const float* wq_b = (const float*)d_in[5];
    const float* wk_w = (const float*)d_in[6];
    const float* wk_b = (const float*)d_in[7];
    const float* wv_w = (const float*)d_in[8];
    const float* wv_b = (const float*)d_in[9];
    const float* wo_w = (const float*)d_in[10];
    const float* wo_b = (const float*)d_in[11];
    float* out = (float*)d_out;

    float* ctx;
    cudaGetSymbolAddress((void**)&ctx, g_ctx);

    __nv_bfloat16 *qhi, *qlo, *khi, *klo, *vhi, *vlo, *chi, *clo;
    __nv_bfloat16 *wqhi, *wqlo, *wkhi, *wklo, *wvhi, *wvlo, *wohi, *wolo;
    __nv_bfloat16 *qshi, *qslo, *kshi, *kslo, *vthi, *vtlo;
    cudaGetSymbolAddress((void**)&qhi, g_qhi);  cudaGetSymbolAddress((void**)&qlo, g_qlo);
    cudaGetSymbolAddress((void**)&khi, g_khi);  cudaGetSymbolAddress((void**)&klo, g_klo);
    cudaGetSymbolAddress((void**)&vhi, g_vhi);  cudaGetSymbolAddress((void**)&vlo, g_vlo);
    cudaGetSymbolAddress((void**)&chi, g_chi);  cudaGetSymbolAddress((void**)&clo, g_clo);
    cudaGetSymbolAddress((void**)&wqhi, g_wqhi); cudaGetSymbolAddress((void**)&wqlo, g_wqlo);
    cudaGetSymbolAddress((void**)&wkhi, g_wkhi); cudaGetSymbolAddress((void**)&wklo, g_wklo);
    cudaGetSymbolAddress((void**)&wvhi, g_wvhi); cudaGetSymbolAddress((void**)&wvlo, g_wvlo);
    cudaGetSymbolAddress((void**)&wohi, g_wohi); cudaGetSymbolAddress((void**)&wolo, g_wolo);
    cudaGetSymbolAddress((void**)&qshi, g_qshi); cudaGetSymbolAddress((void**)&qslo, g_qslo);
    cudaGetSymbolAddress((void**)&kshi, g_kshi); cudaGetSymbolAddress((void**)&kslo, g_kslo);
    cudaGetSymbolAddress((void**)&vthi, g_vthi); cudaGetSymbolAddress((void**)&vtlo, g_vtlo);

    cudaFuncSetAttribute(gemm_mma<0>, cudaFuncAttributeMaxDynamicSharedMemorySize, GEMM_SMEM);
    cudaFuncSetAttribute(gemm_mma<1>, cudaFuncAttributeMaxDynamicSharedMemorySize, GEMM_SMEM);
    cudaFuncSetAttribute(gemm_mma<2>, cudaFuncAttributeMaxDynamicSharedMemorySize, GEMM_SMEM);
    cudaFuncSetAttribute(flash_mma,   cudaFuncAttributeMaxDynamicSharedMemorySize, FLASH_SMEM);

    const int nAct4 = MROWS * DMODEL / 4;
    const int nW4   = DMODEL * DMODEL / 4;

    {
        dim3 ga((nAct4 + 255) / 256, 3);
        split_bf16_multi<<<ga, 256>>>(
            (const float4*)q, (uint2*)qhi, (uint2*)qlo,
            (const float4*)k, (uint2*)khi, (uint2*)klo,
            (const float4*)v, (uint2*)vhi, (uint2*)vlo,
            nullptr, nullptr, nullptr, nAct4);
        dim3 gw((nW4 + 255) / 256, 4);
        split_bf16_multi<<<gw, 256>>>(
            (const float4*)wq_w, (uint2*)wqhi, (uint2*)wqlo,
            (const float4*)wk_w, (uint2*)wkhi, (uint2*)wklo,
            (const float4*)wv_w, (uint2*)wvhi, (uint2*)wvlo,
            (const float4*)wo_w, (uint2*)wohi, (uint2*)wolo, nW4);
    }

    const float qscale = 0.125f * 1.4426950408889634f;

    dim3 ggrid(DMODEL / 128, MROWS / 128);   // (8, 32) = 256 CTAs, one wave @occ2
    gemm_mma<1><<<ggrid, 256, GEMM_SMEM>>>(qhi, qlo, wqhi, wqlo, wq_b, qscale,
                                           nullptr, qshi, qslo);
    gemm_mma<1><<<ggrid, 256, GEMM_SMEM>>>(khi, klo, wkhi, wklo, wk_b, 1.0f,
                                           nullptr, kshi, kslo);
    gemm_mma<2><<<ggrid, 256, GEMM_SMEM>>>(vhi, vlo, wvhi, wvlo, wv_b, 1.0f,
                                           nullptr, vthi, vtlo);

    dim3 agrid(SEQ / 128, BH);               // (16, 32)
    flash_mma<<<agrid, 256, FLASH_SMEM>>>(qshi, qslo, kshi, kslo, vthi, vtlo, ctx);

    {
        dim3 gc((nAct4 + 255) / 256, 1);
        split_bf16_multi<<<gc, 256>>>(
            (const float4*)ctx, (uint2*)chi, (uint2*)clo,
            nullptr, nullptr, nullptr,
            nullptr, nullptr, nullptr,
            nullptr, nullptr, nullptr, nAct4);
    }
    gemm_mma<0><<<ggrid, 256, GEMM_SMEM>>>(chi, clo, wohi, wolo, wo_b, 1.0f,
                                           out, nullptr, nullptr);
}

// round 12
// speedup vs baseline: 1.4350x; 1.4350x over previous
#include <cuda_runtime.h>
#include <cuda_bf16.h>
#include <cstdint>

// Problem constants
#define DMODEL 1024
#define HEADS  16
#define DK     64
#define BATCH  2
#define SEQ    2048
#define MROWS  (BATCH * SEQ)          // 4096
#define BH     (BATCH * HEADS)        // 32

// ---------------- scratch (static device memory; no allocs) ----------------
__device__ __nv_bfloat16 g_qhi[MROWS * DMODEL], g_qlo[MROWS * DMODEL];
__device__ __nv_bfloat16 g_khi[MROWS * DMODEL], g_klo[MROWS * DMODEL];
__device__ __nv_bfloat16 g_vhi[MROWS * DMODEL], g_vlo[MROWS * DMODEL];
__device__ __nv_bfloat16 g_chi[MROWS * DMODEL], g_clo[MROWS * DMODEL];
__device__ __nv_bfloat16 g_wqhi[DMODEL * DMODEL], g_wqlo[DMODEL * DMODEL];
__device__ __nv_bfloat16 g_wkhi[DMODEL * DMODEL], g_wklo[DMODEL * DMODEL];
__device__ __nv_bfloat16 g_wvhi[DMODEL * DMODEL], g_wvlo[DMODEL * DMODEL];
__device__ __nv_bfloat16 g_wohi[DMODEL * DMODEL], g_wolo[DMODEL * DMODEL];
__device__ __nv_bfloat16 g_qshi[BH * SEQ * DK], g_qslo[BH * SEQ * DK]; // [bh][s][dk]
__device__ __nv_bfloat16 g_kshi[BH * SEQ * DK], g_kslo[BH * SEQ * DK]; // [bh][s][dk]
__device__ __nv_bfloat16 g_vthi[BH * DK * SEQ], g_vtlo[BH * DK * SEQ]; // [bh][dk][s]

// ---------------- helpers ---------------------------------------------------
__device__ __forceinline__ void mma16816(float* c, const uint32_t* a, const uint32_t* b) {
    asm volatile(
        "mma.sync.aligned.m16n8k16.row.col.f32.bf16.bf16.f32 "
        "{%0,%1,%2,%3}, {%4,%5,%6,%7}, {%8,%9}, {%0,%1,%2,%3};"
        : "+f"(c[0]), "+f"(c[1]), "+f"(c[2]), "+f"(c[3])
        : "r"(a[0]), "r"(a[1]), "r"(a[2]), "r"(a[3]), "r"(b[0]), "r"(b[1]));
}
__device__ __forceinline__ void ldsm4(uint32_t* r, uint32_t addr) {
    asm volatile("ldmatrix.sync.aligned.m8n8.x4.shared.b16 {%0,%1,%2,%3}, [%4];"
        : "=r"(r[0]), "=r"(r[1]), "=r"(r[2]), "=r"(r[3]) : "r"(addr));
}
__device__ __forceinline__ uint32_t smem_u32(const void* p) {
    uint32_t a;
    asm("{ .reg .u64 t; cvta.to.shared.u64 t, %1; cvt.u32.u64 %0, t; }"
        : "=r"(a) : "l"(p));
    return a;
}
__device__ __forceinline__ void cpa16(uint32_t dst, const void* src) {
    asm volatile("cp.async.cg.shared.global [%0], [%1], 16;" :: "r"(dst), "l"(src));
}
__device__ __forceinline__ void cpa_commit() {
    asm volatile("cp.async.commit_group;" ::: "memory");
}
template <int N>
__device__ __forceinline__ void cpa_wait() {
    asm volatile("cp.async.wait_group %0;" :: "n"(N) : "memory");
}
__device__ __forceinline__ float ex2f(float x) {
    float y; asm("ex2.approx.ftz.f32 %0, %1;" : "=f"(y) : "f"(x)); return y;
}
__device__ __forceinline__ uint32_t pack_bf2(float a, float b) {
    __nv_bfloat162 t = __floats2bfloat162_rn(a, b);
    return *reinterpret_cast<uint32_t*>(&t);
}
// split two floats into packed bf16 hi pair + bf16 lo (residual) pair
__device__ __forceinline__ void split2(float a, float b, uint32_t& hi, uint32_t& lo) {
    __nv_bfloat16 ha = __float2bfloat16(a);
    __nv_bfloat16 hb = __float2bfloat16(b);
    hi = (uint32_t)__bfloat16_as_ushort(ha) |
         ((uint32_t)__bfloat16_as_ushort(hb) << 16);
    lo = pack_bf2(a - __bfloat162float(ha), b - __bfloat162float(hb));
}

// ---------------- split fp32 -> bf16 hi/lo (batched up to 4 tensors) -------
__global__ __launch_bounds__(256) void split_bf16_multi(
    const float4* __restrict__ x0, uint2* __restrict__ h0, uint2* __restrict__ l0,
    const float4* __restrict__ x1, uint2* __restrict__ h1, uint2* __restrict__ l1,
    const float4* __restrict__ x2, uint2* __restrict__ h2, uint2* __restrict__ l2,
    const float4* __restrict__ x3, uint2* __restrict__ h3, uint2* __restrict__ l3,
    int n4)
{
    const int sel = blockIdx.y;
    const float4* x = (sel == 0) ? x0 : (sel == 1) ? x1 : (sel == 2) ? x2 : x3;
    uint2* hi = (sel == 0) ? h0 : (sel == 1) ? h1 : (sel == 2) ? h2 : h3;
    uint2* lo = (sel == 0) ? l0 : (sel == 1) ? l1 : (sel == 2) ? l2 : l3;
    if (x == nullptr) return;

    int i = blockIdx.x * blockDim.x + threadIdx.x;
    if (i >= n4) return;
    float4 v = x[i];
    uint32_t h01, l01, h23, l23;
    split2(v.x, v.y, h01, l01);
    split2(v.z, v.w, h23, l23);
    hi[i] = make_uint2(h01, h23);
    lo[i] = make_uint2(l01, l23);
}

// ---------------- mma.sync bf16 GEMM: Y = (X @ W^T + bias) * scale ---------
// 128x128 tile, warp tile 32(M)x64(N), BK=32 (80B rows — R10 proven layout).
// cp.async 2-stage, issue-after-compute, 2 CTAs/SM.
// INNER LOOPS REORDERED: 8 independent accumulators between reuses (ILP fix).
#define TSTRIDE   80
#define TILE_B    (128 * TSTRIDE)      // 10240
#define GBUF      (4 * TILE_B)         // Ahi|Alo|Bhi|Blo = 40960
#define GEMM_SMEM (2 * GBUF)           // 81920 -> 2 CTAs/SM
#define NCHUNK    32

template <int MODE>
__global__ __launch_bounds__(256, 2) void gemm_mma(
    const __nv_bfloat16* __restrict__ Ahi, const __nv_bfloat16* __restrict__ Alo,
    const __nv_bfloat16* __restrict__ Bhi, const __nv_bfloat16* __restrict__ Blo,
    const float* __restrict__ bias, float scale,
    float* __restrict__ Yf,
    __nv_bfloat16* __restrict__ Yhi, __nv_bfloat16* __restrict__ Ylo)
{
    extern __shared__ __align__(16) char smem_raw[];
    const uint32_t sb = smem_u32(smem_raw);

    const int tid  = threadIdx.x;
    const int wid  = tid >> 5, lane = tid & 31;
    const int wm   = wid & 3;            // 4 warps along M (32 each)
    const int wn   = wid >> 2;           // 2 warps along N (64 each)
    const int qr   = lane >> 2;
    const int qc   = lane & 3;
    const int row0 = blockIdx.y * 128;
    const int col0 = blockIdx.x * 128;

    const int lrow = (lane & 7) + ((lane >> 3) & 1) * 8;
    const int lbyt = (lane >> 4) * 16;

    float acc[2][8][4];                  // warp tile 32x64
#pragma unroll
    for (int a = 0; a < 2; a++)
#pragma unroll
        for (int b = 0; b < 8; b++)
#pragma unroll
            for (int c = 0; c < 4; c++) acc[a][b][c] = 0.f;

    auto cpa_chunk = [&](int c, int buf) {
        const uint32_t db = sb + buf * GBUF;
#pragma unroll
        for (int i = 0; i < 8; i++) {
            const int u   = tid + i * 256;
            const int arr = u >> 9;            // 0=Ahi 1=Alo 2=Bhi 3=Blo
            const int r   = (u & 511) >> 2;
            const int ch  = u & 3;
            const __nv_bfloat16* src =
                (arr == 0) ? Ahi : (arr == 1) ? Alo : (arr == 2) ? Bhi : Blo;
            const int grow = ((arr < 2) ? row0 : col0) + r;
            cpa16(db + arr * TILE_B + r * TSTRIDE + ch * 16,
                  src + (size_t)grow * DMODEL + c * 32 + ch * 8);
        }
        cpa_commit();
    };

    cpa_chunk(0, 0);
    cpa_chunk(1, 1);

#pragma unroll 1
    for (int c = 0; c < NCHUNK; c++) {
        if (c >= NCHUNK - 2) cpa_wait<0>(); else cpa_wait<1>();
        __syncthreads();                  // chunk c visible everywhere

        const uint32_t bb = sb + (c & 1) * GBUF;
#pragma unroll
        for (int ks = 0; ks < 2; ks++) {
            const int kb = ks * 32 + lbyt;

            uint32_t bhf[8][2], blf[8][2];
#pragma unroll
            for (int half = 0; half < 4; half++) {
                const uint32_t addr = bb + 2 * TILE_B
                    + (wn * 64 + half * 16 + lrow) * TSTRIDE + kb;
                uint32_t th[4], tl[4];
                ldsm4(th, addr);
                ldsm4(tl, addr + TILE_B);
                bhf[half * 2 + 0][0] = th[0]; bhf[half * 2 + 1][0] = th[1];
                bhf[half * 2 + 0][1] = th[2]; bhf[half * 2 + 1][1] = th[3];
                blf[half * 2 + 0][0] = tl[0]; blf[half * 2 + 1][0] = tl[1];
                blf[half * 2 + 0][1] = tl[2]; blf[half * 2 + 1][1] = tl[3];
            }
#pragma unroll
            for (int mt = 0; mt < 2; mt++) {
                const uint32_t addr = bb + (wm * 32 + mt * 16 + lrow) * TSTRIDE + kb;
                uint32_t ah[4], al[4];
                ldsm4(ah, addr);
                ldsm4(al, addr + TILE_B);
                // ILP: 8 independent accumulators per product sweep
#pragma unroll
                for (int nt = 0; nt < 8; nt++) mma16816(acc[mt][nt], ah, bhf[nt]);
#pragma unroll
                for (int nt = 0; nt < 8; nt++) mma16816(acc[mt][nt], ah, blf[nt]);
#pragma unroll
                for (int nt = 0; nt < 8; nt++) mma16816(acc[mt][nt], al, bhf[nt]);
            }
        }
        __syncthreads();                  // all warps done with buf (c&1)
        if (c + 2 < NCHUNK) cpa_chunk(c + 2, (c & 1));
    }

    // ---- epilogue ----
#pragma unroll
    for (int mt = 0; mt < 2; mt++) {
#pragma unroll
        for (int nt = 0; nt < 8; nt++) {
            const int col = col0 + wn * 64 + nt * 8 + qc * 2;
            float2 bv = *(const float2*)&bias[col];
#pragma unroll
            for (int h = 0; h < 2; h++) {
                const int m = row0 + wm * 32 + mt * 16 + qr + h * 8;
                float v0 = (acc[mt][nt][h * 2 + 0] + bv.x) * scale;
                float v1 = (acc[mt][nt][h * 2 + 1] + bv.y) * scale;
                if (MODE == 0) {
                    float2 r; r.x = v0; r.y = v1;
                    *(float2*)(Yf + (size_t)m * DMODEL + col) = r;
                } else {
                    const int b  = m >> 11, s = m & (SEQ - 1);
                    const int hh = col >> 6, dk = col & 63;
                    uint32_t hp, lp;
                    split2(v0, v1, hp, lp);
                    if (MODE == 1) {
                        const size_t idx = ((size_t)(b * HEADS + hh) * SEQ + s) * DK + dk;
                        *(uint32_t*)(Yhi + idx) = hp;
                        *(uint32_t*)(Ylo + idx) = lp;
                    } else {           // MODE 2: transposed [bh][dk][s]
                        const size_t base = ((size_t)(b * HEADS + hh) * DK + dk) * SEQ + s;
                        Yhi[base]       = __ushort_as_bfloat16((unsigned short)(hp & 0xffff));
                        Yhi[base + SEQ] = __ushort_as_bfloat16((unsigned short)(hp >> 16));
                        Ylo[base]       = __ushort_as_bfloat16((unsigned short)(lp & 0xffff));
                        Ylo[base + SEQ] = __ushort_as_bfloat16((unsigned short)(lp >> 16));
                    }
                }
            }
        }
    }
}

// ---------------- tensor-core flash attention -------------------------------
// R10 structure (3-stage cp.async KV, one barrier/tile) + ILP-reordered mma
// loops + fused bf16 hi/lo split epilogue (writes chi/clo directly).
#define ATS    144
#define KTILE  (64 * ATS)              // 9216
#define FBUF   (4 * KTILE)             // Khi|Klo|Vthi|Vtlo = 36864
#define FLASH_SMEM (3 * FBUF)          // 110592
#define NT     (SEQ / 64)              // 32

__global__ __launch_bounds__(256) void flash_mma(
    const __nv_bfloat16* __restrict__ Qhi, const __nv_bfloat16* __restrict__ Qlo,
    const __nv_bfloat16* __restrict__ Khi, const __nv_bfloat16* __restrict__ Klo,
    const __nv_bfloat16* __restrict__ Vthi, const __nv_bfloat16* __restrict__ Vtlo,
    __nv_bfloat16* __restrict__ Chi, __nv_bfloat16* __restrict__ Clo)
{
    extern __shared__ __align__(16) char sm[];
    const uint32_t sbf = smem_u32(sm);

    const int tid = threadIdx.x, wid = tid >> 5, lane = tid & 31;
    const int qr = lane >> 2, qc = lane & 3;
    const int bh = blockIdx.y;
    const int s0 = blockIdx.x * 128;
    const int b  = bh >> 4, h = bh & 15;

    // ---- stage Q tile (hi at 0, lo at 2*KTILE), extract A-fragments ----
#pragma unroll
    for (int i = 0; i < 8; i++) {
        int u = tid + i * 256;          // 0..2047
        int arr = u >> 10;              // 0=hi 1=lo
        int idx = u & 1023, r = idx >> 3, ch = idx & 7;
        const __nv_bfloat16* src = arr ? Qlo : Qhi;
        *(float4*)(sm + arr * 2 * KTILE + r * ATS + ch * 16) =
            *(const float4*)(src + ((size_t)bh * SEQ + s0 + r) * DK + ch * 8);
    }
    __syncthreads();
    uint32_t qfh[4][4], qfl[4][4];
    {
        const char* base = sm + (wid * 16 + qr) * ATS;
#pragma unroll
        for (int kt = 0; kt < 4; kt++) {
            const int off = kt * 32 + qc * 4;
            qfh[kt][0] = *(const uint32_t*)(base + off);
            qfh[kt][1] = *(const uint32_t*)(base + 8 * ATS + off);
            qfh[kt][2] = *(const uint32_t*)(base + off + 16);
            qfh[kt][3] = *(const uint32_t*)(base + 8 * ATS + off + 16);
            qfl[kt][0] = *(const uint32_t*)(base + 2 * KTILE + off);
            qfl[kt][1] = *(const uint32_t*)(base + 2 * KTILE + 8 * ATS + off);
            qfl[kt][2] = *(const uint32_t*)(base + 2 * KTILE + off + 16);
            qfl[kt][3] = *(const uint32_t*)(base + 2 * KTILE + 8 * ATS + off + 16);
        }
    }
    __syncthreads();                    // Q fully consumed before buf0 reuse

    float O[8][4];
#pragma unroll
    for (int nt = 0; nt < 8; nt++)
#pragma unroll
        for (int c = 0; c < 4; c++) O[nt][c] = 0.f;
    float m0 = -1e30f, m1 = -1e30f, l0 = 0.f, l1 = 0.f;

    auto cpaKV = [&](int t, int buf) {
        const uint32_t db = sbf + buf * FBUF;
        const int j0 = t * 64;
#pragma unroll
        for (int i = 0; i < 8; i++) {
            int u = tid + i * 256;
            int arr = u >> 9;           // 0=Khi 1=Klo 2=Vthi 3=Vtlo
            int idx = u & 511, r = idx >> 3, ch = idx & 7;
            const __nv_bfloat16* src =
                (arr == 0) ? Khi : (arr == 1) ? Klo : (arr == 2) ? Vthi : Vtlo;
            size_t g = (arr < 2)
                ? (((size_t)bh * SEQ + j0 + r) * DK + ch * 8)
                : (((size_t)bh * DK + r) * SEQ + j0 + ch * 8);
            cpa16(db + arr * KTILE + r * ATS + ch * 16, src + g);
        }
        cpa_commit();
    };

    cpaKV(0, 0);
    cpaKV(1, 1);

#pragma unroll 1
    for (int t = 0; t < NT; t++) {
        if (t == NT - 1) cpa_wait<0>(); else cpa_wait<1>();
        __syncthreads();
        if (t + 2 < NT) cpaKV(t + 2, (t + 2) % 3);
        const char* smb = sm + (t % 3) * FBUF;

        // ---- S = Q K^T (3-product split), base-2 domain ----
        float S[8][4];
#pragma unroll
        for (int nt = 0; nt < 8; nt++)
#pragma unroll
            for (int c = 0; c < 4; c++) S[nt][c] = 0.f;

#pragma unroll
        for (int kt = 0; kt < 4; kt++) {
            const int kb = kt * 32 + qc * 4;
            uint32_t kbh[8][2], kbl[8][2];
#pragma unroll
            for (int nt = 0; nt < 8; nt++) {
                const char* kp = smb + (nt * 8 + qr) * ATS + kb;
                kbh[nt][0] = *(const uint32_t*)kp;
                kbh[nt][1] = *(const uint32_t*)(kp + 16);
                kbl[nt][0] = *(const uint32_t*)(kp + KTILE);
                kbl[nt][1] = *(const uint32_t*)(kp + KTILE + 16);
            }
            // ILP: sweep 8 independent accumulators per product
#pragma unroll
            for (int nt = 0; nt < 8; nt++) mma16816(S[nt], qfh[kt], kbh[nt]);
#pragma unroll
            for (int nt = 0; nt < 8; nt++) mma16816(S[nt], qfh[kt], kbl[nt]);
#pragma unroll
            for (int nt = 0; nt < 8; nt++) mma16816(S[nt], qfl[kt], kbh[nt]);
        }

        // ---- online softmax (base 2) ----
        float rx0 = -1e30f, rx1 = -1e30f;
#pragma unroll
        for (int nt = 0; nt < 8; nt++) {
            rx0 = fmaxf(rx0, fmaxf(S[nt][0], S[nt][1]));
            rx1 = fmaxf(rx1, fmaxf(S[nt][2], S[nt][3]));
        }
        rx0 = fmaxf(rx0, __shfl_xor_sync(0xffffffffu, rx0, 1));
        rx0 = fmaxf(rx0, __shfl_xor_sync(0xffffffffu, rx0, 2));
        rx1 = fmaxf(rx1, __shfl_xor_sync(0xffffffffu, rx1, 1));
        rx1 = fmaxf(rx1, __shfl_xor_sync(0xffffffffu, rx1, 2));

        const float mn0 = fmaxf(m0, rx0);
        const float mn1 = fmaxf(m1, rx1);
        const float a0 = ex2f(m0 - mn0);
        const float a1 = ex2f(m1 - mn1);
        m0 = mn0; m1 = mn1;
        l0 *= a0;  l1 *= a1;

#pragma unroll
        for (int nt = 0; nt < 8; nt++) {
            S[nt][0] = ex2f(S[nt][0] - m0);
            S[nt][1] = ex2f(S[nt][1] - m0);
            S[nt][2] = ex2f(S[nt][2] - m1);
            S[nt][3] = ex2f(S[nt][3] - m1);
            l0 += S[nt][0] + S[nt][1];
            l1 += S[nt][2] + S[nt][3];
            O[nt][0] *= a0; O[nt][1] *= a0;
            O[nt][2] *= a1; O[nt][3] *= a1;
        }

        // ---- O += P V (P split hi/lo in registers) ----
#pragma unroll
        for (int kt = 0; kt < 4; kt++) {
            uint32_t ah[4], al[4];
#pragma unroll
            for (int half = 0; half < 2; half++) {
                const float* sv = S[2 * kt + half];
                split2(sv[0], sv[1], ah[half * 2 + 0], al[half * 2 + 0]);
                split2(sv[2], sv[3], ah[half * 2 + 1], al[half * 2 + 1]);
            }

            const int kb = kt * 32 + qc * 4;
            uint32_t vbh[8][2], vbl[8][2];
#pragma unroll
            for (int nt = 0; nt < 8; nt++) {
                const char* vp = smb + 2 * KTILE + (nt * 8 + qr) * ATS + kb;
                vbh[nt][0] = *(const uint32_t*)vp;
                vbh[nt][1] = *(const uint32_t*)(vp + 16);
                vbl[nt][0] = *(const uint32_t*)(vp + KTILE);
                vbl[nt][1] = *(const uint32_t*)(vp + KTILE + 16);
            }
#pragma unroll
            for (int nt = 0; nt < 8; nt++) mma16816(O[nt], ah, vbh[nt]);
#pragma unroll
            for (int nt = 0; nt < 8; nt++) mma16816(O[nt], ah, vbl[nt]);
#pragma unroll
            for (int nt = 0; nt < 8; nt++) mma16816(O[nt], al, vbh[nt]);
        }
    }

    // ---- finalize: normalize + fused bf16 hi/lo split store ----
    l0 += __shfl_xor_sync(0xffffffffu, l0, 1);
    l0 += __shfl_xor_sync(0xffffffffu, l0, 2);
    l1 += __shfl_xor_sync(0xffffffffu, l1, 1);
    l1 += __shfl_xor_sync(0xffffffffu, l1, 2);
    const float inv0 = 1.f / l0, inv1 = 1.f / l1;

    const int s = s0 + wid * 16 + qr;
#pragma unroll
    for (int nt = 0; nt < 8; nt++) {
        const int col = h * DK + nt * 8 + qc * 2;
        const size_t i0 = ((size_t)(b * SEQ + s)    ) * DMODEL + col;
        const size_t i1 = ((size_t)(b * SEQ + s + 8)) * DMODEL + col;
        uint32_t hp, lp;
        split2(O[nt][0] * inv0, O[nt][1] * inv0, hp, lp);
        *(uint32_t*)(Chi + i0) = hp;
        *(uint32_t*)(Clo + i0) = lp;
        split2(O[nt][2] * inv1, O[nt][3] * inv1, hp, lp);
        *(uint32_t*)(Chi + i1) = hp;
        *(uint32_t*)(Clo + i1) = lp;
    }
}

// ---------------- launch ---------------------------------------------------
extern "C" void kernel_launch(void* const* d_in, const int* in_sizes, int n_in,
                              void* d_out, int out_size)
{
    (void)in_sizes; (void)n_in; (void)out_size;
    const float* q    = (const float*)d_in[0];
    const float* k    = (const float*)d_in[1];
    const float* v    = (const float*)d_in[2];
    const float* wq_w = (const float*)d_in[4];
    const float* wq_b = (const float*)d_in[5];
    const float* wk_w = (const float*)d_in[6];
    const float* wk_b = (const float*)d_in[7];
    const float* wv_w = (const float*)d_in[8];
    const float* wv_b = (const float*)d_in[9];
    const float* wo_w = (const float*)d_in[10];
    const float* wo_b = (const float*)d_in[11];
    float* out = (float*)d_out;

    __nv_bfloat16 *qhi, *qlo, *khi, *klo, *vhi, *vlo, *chi, *clo;
    __nv_bfloat16 *wqhi, *wqlo, *wkhi, *wklo, *wvhi, *wvlo, *wohi, *wolo;
    __nv_bfloat16 *qshi, *qslo, *kshi, *kslo, *vthi, *vtlo;
    cudaGetSymbolAddress((void**)&qhi, g_qhi);  cudaGetSymbolAddress((void**)&qlo, g_qlo);
    cudaGetSymbolAddress((void**)&khi, g_khi);  cudaGetSymbolAddress((void**)&klo, g_klo);
    cudaGetSymbolAddress((void**)&vhi, g_vhi);  cudaGetSymbolAddress((void**)&vlo, g_vlo);
    cudaGetSymbolAddress((void**)&chi, g_chi);  cudaGetSymbolAddress((void**)&clo, g_clo);
    cudaGetSymbolAddress((void**)&wqhi, g_wqhi); cudaGetSymbolAddress((void**)&wqlo, g_wqlo);
    cudaGetSymbolAddress((void**)&wkhi, g_wkhi); cudaGetSymbolAddress((void**)&wklo, g_wklo);
    cudaGetSymbolAddress((void**)&wvhi, g_wvhi); cudaGetSymbolAddress((void**)&wvlo, g_wvlo);
    cudaGetSymbolAddress((void**)&wohi, g_wohi); cudaGetSymbolAddress((void**)&wolo, g_wolo);
    cudaGetSymbolAddress((void**)&qshi, g_qshi); cudaGetSymbolAddress((void**)&qslo, g_qslo);
    cudaGetSymbolAddress((void**)&kshi, g_kshi); cudaGetSymbolAddress((void**)&kslo, g_kslo);
    cudaGetSymbolAddress((void**)&vthi, g_vthi); cudaGetSymbolAddress((void**)&vtlo, g_vtlo);

    cudaFuncSetAttribute(gemm_mma<0>, cudaFuncAttributeMaxDynamicSharedMemorySize, GEMM_SMEM);
    cudaFuncSetAttribute(gemm_mma<1>, cudaFuncAttributeMaxDynamicSharedMemorySize, GEMM_SMEM);
    cudaFuncSetAttribute(gemm_mma<2>, cudaFuncAttributeMaxDynamicSharedMemorySize, GEMM_SMEM);
    cudaFuncSetAttribute(flash_mma,   cudaFuncAttributeMaxDynamicSharedMemorySize, FLASH_SMEM);

    const int nAct4 = MROWS * DMODEL / 4;
    const int nW4   = DMODEL * DMODEL / 4;

    {
        dim3 ga((nAct4 + 255) / 256, 3);
        split_bf16_multi<<<ga, 256>>>(
            (const float4*)q, (uint2*)qhi, (uint2*)qlo,
            (const float4*)k, (uint2*)khi, (uint2*)klo,
            (const float4*)v, (uint2*)vhi, (uint2*)vlo,
            nullptr, nullptr, nullptr, nAct4);
        dim3 gw((nW4 + 255) / 256, 4);
        split_bf16_multi<<<gw, 256>>>(
            (const float4*)wq_w, (uint2*)wqhi, (uint2*)wqlo,
            (const float4*)wk_w, (uint2*)wkhi, (uint2*)wklo,
            (const float4*)wv_w, (uint2*)wvhi, (uint2*)wvlo,
            (const float4*)wo_w, (uint2*)wohi, (uint2*)wolo, nW4);
    }

    const float qscale = 0.125f * 1.4426950408889634f;

    dim3 ggrid(DMODEL / 128, MROWS / 128);   // (8, 32) = 256 CTAs, one wave @occ2
    gemm_mma<1><<<ggrid, 256, GEMM_SMEM>>>(qhi, qlo, wqhi, wqlo, wq_b, qscale,
                                           nullptr, qshi, qslo);
    gemm_mma<1><<<ggrid, 256, GEMM_SMEM>>>(khi, klo, wkhi, wklo, wk_b, 1.0f,
                                           nullptr, kshi, kslo);
    gemm_mma<2><<<ggrid, 256, GEMM_SMEM>>>(vhi, vlo, wvhi, wvlo, wv_b, 1.0f,
                                           nullptr, vthi, vtlo);

    dim3 agrid(SEQ / 128, BH);               // (16, 32)
    flash_mma<<<agrid, 256, FLASH_SMEM>>>(qshi, qslo, kshi, kslo, vthi, vtlo,
                                          chi, clo);

    gemm_mma<0><<<ggrid, 256, GEMM_SMEM>>>(chi, clo, wohi, wolo, wo_b, 1.0f,
                                           out, nullptr, nullptr);
}

// round 14
// speedup vs baseline: 1.9556x; 1.3627x over previous
#include <cuda_runtime.h>
#include <cuda_bf16.h>
#include <cuda_fp16.h>
#include <cstdint>

// Problem constants
#define DMODEL 1024
#define HEADS  16
#define DK     64
#define BATCH  2
#define SEQ    2048
#define MROWS  (BATCH * SEQ)          // 4096
#define BH     (BATCH * HEADS)        // 32

// ---------------- scratch (static device memory; no allocs) ----------------
// fp16 activation splits (hi+lo) and single-fp16 weights
__device__ __half g_qhi[MROWS * DMODEL], g_qlo[MROWS * DMODEL];
__device__ __half g_khi[MROWS * DMODEL], g_klo[MROWS * DMODEL];
__device__ __half g_vhi[MROWS * DMODEL], g_vlo[MROWS * DMODEL];
__device__ __half g_chi[MROWS * DMODEL], g_clo[MROWS * DMODEL];
__device__ __half g_wqh[DMODEL * DMODEL];
__device__ __half g_wkh[DMODEL * DMODEL];
__device__ __half g_wvh[DMODEL * DMODEL];
__device__ __half g_woh[DMODEL * DMODEL];
// projection outputs
__device__ __half g_qsh[BH * SEQ * DK], g_qsl[BH * SEQ * DK]; // Q split [bh][s][dk]
__device__ __half g_ksh[BH * SEQ * DK];                        // K single [bh][s][dk]
__device__ __half g_vth[BH * DK * SEQ];                        // V single [bh][dk][s]

// ---------------- helpers ---------------------------------------------------
__device__ __forceinline__ void mma16816(float* c, const uint32_t* a, const uint32_t* b) {
    asm volatile(
        "mma.sync.aligned.m16n8k16.row.col.f32.f16.f16.f32 "
        "{%0,%1,%2,%3}, {%4,%5,%6,%7}, {%8,%9}, {%0,%1,%2,%3};"
        : "+f"(c[0]), "+f"(c[1]), "+f"(c[2]), "+f"(c[3])
        : "r"(a[0]), "r"(a[1]), "r"(a[2]), "r"(a[3]), "r"(b[0]), "r"(b[1]));
}
__device__ __forceinline__ void ldsm4(uint32_t* r, uint32_t addr) {
    asm volatile("ldmatrix.sync.aligned.m8n8.x4.shared.b16 {%0,%1,%2,%3}, [%4];"
        : "=r"(r[0]), "=r"(r[1]), "=r"(r[2]), "=r"(r[3]) : "r"(addr));
}
__device__ __forceinline__ uint32_t smem_u32(const void* p) {
    uint32_t a;
    asm("{ .reg .u64 t; cvta.to.shared.u64 t, %1; cvt.u32.u64 %0, t; }"
        : "=r"(a) : "l"(p));
    return a;
}
__device__ __forceinline__ void cpa16(uint32_t dst, const void* src) {
    asm volatile("cp.async.cg.shared.global [%0], [%1], 16;" :: "r"(dst), "l"(src));
}
__device__ __forceinline__ void cpa_commit() {
    asm volatile("cp.async.commit_group;" ::: "memory");
}
template <int N>
__device__ __forceinline__ void cpa_wait() {
    asm volatile("cp.async.wait_group %0;" :: "n"(N) : "memory");
}
__device__ __forceinline__ float ex2f(float x) {
    float y; asm("ex2.approx.ftz.f32 %0, %1;" : "=f"(y) : "f"(x)); return y;
}
// pack two fp16
__device__ __forceinline__ uint32_t packh2(__half a, __half b) {
    __half2 t = __halves2half2(a, b);
    return *reinterpret_cast<uint32_t*>(&t);
}
// split two floats into fp16 hi pair + fp16 residual pair
__device__ __forceinline__ void split2h(float a, float b, uint32_t& hi, uint32_t& lo) {
    __half ha = __float2half_rn(a);
    __half hb = __float2half_rn(b);
    hi = packh2(ha, hb);
    lo = packh2(__float2half_rn(a - __half2float(ha)),
                __float2half_rn(b - __half2float(hb)));
}

// ---------------- fp32 -> fp16 split / convert (batched up to 4 tensors) ---
// lo pointer == nullptr -> convert-only (weights)
__global__ __launch_bounds__(256) void split_fp16_multi(
    const float4* __restrict__ x0, uint2* __restrict__ h0, uint2* __restrict__ l0,
    const float4* __restrict__ x1, uint2* __restrict__ h1, uint2* __restrict__ l1,
    const float4* __restrict__ x2, uint2* __restrict__ h2, uint2* __restrict__ l2,
    const float4* __restrict__ x3, uint2* __restrict__ h3, uint2* __restrict__ l3,
    int n4)
{
    const int sel = blockIdx.y;
    const float4* x = (sel == 0) ? x0 : (sel == 1) ? x1 : (sel == 2) ? x2 : x3;
    uint2* hi = (sel == 0) ? h0 : (sel == 1) ? h1 : (sel == 2) ? h2 : h3;
    uint2* lo = (sel == 0) ? l0 : (sel == 1) ? l1 : (sel == 2) ? l2 : l3;
    if (x == nullptr) return;

    int i = blockIdx.x * blockDim.x + threadIdx.x;
    if (i >= n4) return;
    float4 v = x[i];
    if (lo != nullptr) {
        uint32_t h01, l01, h23, l23;
        split2h(v.x, v.y, h01, l01);
        split2h(v.z, v.w, h23, l23);
        hi[i] = make_uint2(h01, h23);
        lo[i] = make_uint2(l01, l23);
    } else {
        hi[i] = make_uint2(packh2(__float2half_rn(v.x), __float2half_rn(v.y)),
                           packh2(__float2half_rn(v.z), __float2half_rn(v.w)));
    }
}

// ---------------- fp16 2-product GEMM: Y = (X @ W^T + bias) * scale --------
// X split (Ah+Al), W single (Bh):  acc = Ah*Bh + Al*Bh.
// 128x128 tile, warp 32(M)x64(N), BK=32, 80B rows, cp.async 2-stage
// issue-after-compute (R10-proven structure), 2 CTAs/SM.
// MODE 0: fp32 out. MODE 1: fp16 split headsplit (Q). MODE 3: fp16 single
// headsplit (K). MODE 2: fp16 single transposed headsplit (V).
#define TSTRIDE   80
#define TILE_B    (128 * TSTRIDE)      // 10240
#define GBUF      (3 * TILE_B)         // Ah|Al|Bh = 30720
#define GEMM_SMEM (2 * GBUF)           // 61440 -> 2 CTAs/SM
#define NCHUNK    32

template <int MODE>
__global__ __launch_bounds__(256, 2) void gemm_mma(
    const __half* __restrict__ Ah, const __half* __restrict__ Al,
    const __half* __restrict__ Bh,
    const float* __restrict__ bias, float scale,
    float* __restrict__ Yf,
    __half* __restrict__ Yh, __half* __restrict__ Yl)
{
    extern __shared__ __align__(16) char smem_raw[];
    const uint32_t sb = smem_u32(smem_raw);

    const int tid  = threadIdx.x;
    const int wid  = tid >> 5, lane = tid & 31;
    const int wm   = wid & 3;            // 4 warps along M (32 each)
    const int wn   = wid >> 2;           // 2 warps along N (64 each)
    const int qr   = lane >> 2;
    const int qc   = lane & 3;
    const int row0 = blockIdx.y * 128;
    const int col0 = blockIdx.x * 128;

    const int lrow = (lane & 7) + ((lane >> 3) & 1) * 8;
    const int lbyt = (lane >> 4) * 16;

    float acc[2][8][4];
#pragma unroll
    for (int a = 0; a < 2; a++)
#pragma unroll
        for (int b = 0; b < 8; b++)
#pragma unroll
            for (int c = 0; c < 4; c++) acc[a][b][c] = 0.f;

    // 1536 x 16B transfers per chunk -> 6 per thread
    auto cpa_chunk = [&](int c, int buf) {
        const uint32_t db = sb + buf * GBUF;
#pragma unroll
        for (int i = 0; i < 6; i++) {
            const int u   = tid + i * 256;
            const int arr = u >> 9;            // 0=Ah 1=Al 2=Bh
            const int r   = (u & 511) >> 2;
            const int ch  = u & 3;
            const __half* src = (arr == 0) ? Ah : (arr == 1) ? Al : Bh;
            const int grow = ((arr < 2) ? row0 : col0) + r;
            cpa16(db + arr * TILE_B + r * TSTRIDE + ch * 16,
                  src + (size_t)grow * DMODEL + c * 32 + ch * 8);
        }
        cpa_commit();
    };

    cpa_chunk(0, 0);
    cpa_chunk(1, 1);

#pragma unroll 1
    for (int c = 0; c < NCHUNK; c++) {
        if (c >= NCHUNK - 2) cpa_wait<0>(); else cpa_wait<1>();
        __syncthreads();                  // chunk c visible everywhere

        const uint32_t bb = sb + (c & 1) * GBUF;
#pragma unroll
        for (int ks = 0; ks < 2; ks++) {
            const int kb = ks * 32 + lbyt;

            uint32_t bf[8][2];
#pragma unroll
            for (int half = 0; half < 4; half++) {
                const uint32_t addr = bb + 2 * TILE_B
                    + (wn * 64 + half * 16 + lrow) * TSTRIDE + kb;
                uint32_t th[4];
                ldsm4(th, addr);
                bf[half * 2 + 0][0] = th[0]; bf[half * 2 + 1][0] = th[1];
                bf[half * 2 + 0][1] = th[2]; bf[half * 2 + 1][1] = th[3];
            }
#pragma unroll
            for (int mt = 0; mt < 2; mt++) {
                const uint32_t addr = bb + (wm * 32 + mt * 16 + lrow) * TSTRIDE + kb;
                uint32_t ah[4], al[4];
                ldsm4(ah, addr);
                ldsm4(al, addr + TILE_B);
#pragma unroll
                for (int nt = 0; nt < 8; nt++) {
                    mma16816(acc[mt][nt], ah, bf[nt]);
                    mma16816(acc[mt][nt], al, bf[nt]);
                }
            }
        }
        __syncthreads();                  // all warps done with buf (c&1)
        if (c + 2 < NCHUNK) cpa_chunk(c + 2, (c & 1));
    }

    // ---- epilogue ----
#pragma unroll
    for (int mt = 0; mt < 2; mt++) {
#pragma unroll
        for (int nt = 0; nt < 8; nt++) {
            const int col = col0 + wn * 64 + nt * 8 + qc * 2;
            float2 bv = *(const float2*)&bias[col];
#pragma unroll
            for (int h = 0; h < 2; h++) {
                const int m = row0 + wm * 32 + mt * 16 + qr + h * 8;
                float v0 = (acc[mt][nt][h * 2 + 0] + bv.x) * scale;
                float v1 = (acc[mt][nt][h * 2 + 1] + bv.y) * scale;
                if (MODE == 0) {
                    float2 r; r.x = v0; r.y = v1;
                    *(float2*)(Yf + (size_t)m * DMODEL + col) = r;
                } else {
                    const int b  = m >> 11, s = m & (SEQ - 1);
                    const int hh = col >> 6, dk = col & 63;
                    if (MODE == 1) {           // Q: split fp16
                        uint32_t hp, lp;
                        split2h(v0, v1, hp, lp);
                        const size_t idx = ((size_t)(b * HEADS + hh) * SEQ + s) * DK + dk;
                        *(uint32_t*)(Yh + idx) = hp;
                        *(uint32_t*)(Yl + idx) = lp;
                    } else if (MODE == 3) {    // K: single fp16
                        const size_t idx = ((size_t)(b * HEADS + hh) * SEQ + s) * DK + dk;
                        *(uint32_t*)(Yh + idx) =
                            packh2(__float2half_rn(v0), __float2half_rn(v1));
                    } else {                   // MODE 2: V single fp16, [bh][dk][s]
                        const size_t base = ((size_t)(b * HEADS + hh) * DK + dk) * SEQ + s;
                        Yh[base]       = __float2half_rn(v0);
                        Yh[base + SEQ] = __float2half_rn(v1);
                    }
                }
            }
        }
    }
}

// ---------------- fp16 2-product flash attention ----------------------------
// Q split (qh+ql) x K single; P split (register) x V single.
// R10 pipeline structure: 3-stage cp.async KV, one barrier per tile.
// Fused epilogue: ctx written as fp16 split (Chi, Clo).
#define ATS    144
#define KTILE  (64 * ATS)              // 9216
#define QTILE  (128 * ATS)             // 18432
#define FBUF   (2 * KTILE)             // Kh|Vth = 18432
#define FLASH_SMEM (3 * FBUF)          // 55296 (>= 2*QTILE for Q staging)
#define NT     (SEQ / 64)              // 32

__global__ __launch_bounds__(256) void flash_mma(
    const __half* __restrict__ Qh, const __half* __restrict__ Ql,
    const __half* __restrict__ Kh, const __half* __restrict__ Vth,
    __half* __restrict__ Chi, __half* __restrict__ Clo)
{
    extern __shared__ __align__(16) char sm[];
    const uint32_t sbf = smem_u32(sm);

    const int tid = threadIdx.x, wid = tid >> 5, lane = tid & 31;
    const int qr = lane >> 2, qc = lane & 3;
    const int bh = blockIdx.y;
    const int s0 = blockIdx.x * 128;
    const int b  = bh >> 4, h = bh & 15;

    // ---- stage Q tile (qh at 0, ql at QTILE), extract A-fragments ----
#pragma unroll
    for (int i = 0; i < 8; i++) {
        int u = tid + i * 256;          // 0..2047
        int arr = u >> 10;              // 0=hi 1=lo
        int idx = u & 1023, r = idx >> 3, ch = idx & 7;
        const __half* src = arr ? Ql : Qh;
        *(float4*)(sm + arr * QTILE + r * ATS + ch * 16) =
            *(const float4*)(src + ((size_t)bh * SEQ + s0 + r) * DK + ch * 8);
    }
    __syncthreads();
    uint32_t qfh[4][4], qfl[4][4];
    {
        const char* base = sm + (wid * 16 + qr) * ATS;
#pragma unroll
        for (int kt = 0; kt < 4; kt++) {
            const int off = kt * 32 + qc * 4;
            qfh[kt][0] = *(const uint32_t*)(base + off);
            qfh[kt][1] = *(const uint32_t*)(base + 8 * ATS + off);
            qfh[kt][2] = *(const uint32_t*)(base + off + 16);
            qfh[kt][3] = *(const uint32_t*)(base + 8 * ATS + off + 16);
            qfl[kt][0] = *(const uint32_t*)(base + QTILE + off);
            qfl[kt][1] = *(const uint32_t*)(base + QTILE + 8 * ATS + off);
            qfl[kt][2] = *(const uint32_t*)(base + QTILE + off + 16);
            qfl[kt][3] = *(const uint32_t*)(base + QTILE + 8 * ATS + off + 16);
        }
    }
    __syncthreads();                    // Q fully consumed before buffer reuse

    float O[8][4];
#pragma unroll
    for (int nt = 0; nt < 8; nt++)
#pragma unroll
        for (int c = 0; c < 4; c++) O[nt][c] = 0.f;
    float m0 = -1e30f, m1 = -1e30f, l0 = 0.f, l1 = 0.f;

    // 1024 x 16B per tile -> 4 per thread
    auto cpaKV = [&](int t, int buf) {
        const uint32_t db = sbf + buf * FBUF;
        const int j0 = t * 64;
#pragma unroll
        for (int i = 0; i < 4; i++) {
            int u = tid + i * 256;
            int arr = u >> 9;           // 0=Kh 1=Vth
            int idx = u & 511, r = idx >> 3, ch = idx & 7;
            const __half* src = arr ? Vth : Kh;
            size_t g = (arr == 0)
                ? (((size_t)bh * SEQ + j0 + r) * DK + ch * 8)
                : (((size_t)bh * DK + r) * SEQ + j0 + ch * 8);
            cpa16(db + arr * KTILE + r * ATS + ch * 16, src + g);
        }
        cpa_commit();
    };

    cpaKV(0, 0);
    cpaKV(1, 1);

#pragma unroll 1
    for (int t = 0; t < NT; t++) {
        if (t == NT - 1) cpa_wait<0>(); else cpa_wait<1>();
        __syncthreads();
        if (t + 2 < NT) cpaKV(t + 2, (t + 2) % 3);
        const char* smb = sm + (t % 3) * FBUF;

        // ---- S = Q K^T (2-product fp16), base-2 domain ----
        float S[8][4];
#pragma unroll
        for (int nt = 0; nt < 8; nt++)
#pragma unroll
            for (int c = 0; c < 4; c++) S[nt][c] = 0.f;

#pragma unroll
        for (int kt = 0; kt < 4; kt++) {
            const int kb = kt * 32 + qc * 4;
#pragma unroll
            for (int nt = 0; nt < 8; nt++) {
                const char* kp = smb + (nt * 8 + qr) * ATS + kb;
                uint32_t kf[2];
                kf[0] = *(const uint32_t*)kp;
                kf[1] = *(const uint32_t*)(kp + 16);
                mma16816(S[nt], qfh[kt], kf);
                mma16816(S[nt], qfl[kt], kf);
            }
        }

        // ---- online softmax (base 2) ----
        float rx0 = -1e30f, rx1 = -1e30f;
#pragma unroll
        for (int nt = 0; nt < 8; nt++) {
            rx0 = fmaxf(rx0, fmaxf(S[nt][0], S[nt][1]));
            rx1 = fmaxf(rx1, fmaxf(S[nt][2], S[nt][3]));
        }
        rx0 = fmaxf(rx0, __shfl_xor_sync(0xffffffffu, rx0, 1));
        rx0 = fmaxf(rx0, __shfl_xor_sync(0xffffffffu, rx0, 2));
        rx1 = fmaxf(rx1, __shfl_xor_sync(0xffffffffu, rx1, 1));
        rx1 = fmaxf(rx1, __shfl_xor_sync(0xffffffffu, rx1, 2));

        const float mn0 = fmaxf(m0, rx0);
        const float mn1 = fmaxf(m1, rx1);
        const float a0 = ex2f(m0 - mn0);
        const float a1 = ex2f(m1 - mn1);
        m0 = mn0; m1 = mn1;
        l0 *= a0;  l1 *= a1;

#pragma unroll
        for (int nt = 0; nt < 8; nt++) {
            S[nt][0] = ex2f(S[nt][0] - m0);
            S[nt][1] = ex2f(S[nt][1] - m0);
            S[nt][2] = ex2f(S[nt][2] - m1);
            S[nt][3] = ex2f(S[nt][3] - m1);
            l0 += S[nt][0] + S[nt][1];
            l1 += S[nt][2] + S[nt][3];
            O[nt][0] *= a0; O[nt][1] *= a0;
            O[nt][2] *= a1; O[nt][3] *= a1;
        }

        // ---- O += P V (P split fp16 in registers, V single) ----
#pragma unroll
        for (int kt = 0; kt < 4; kt++) {
            uint32_t ah[4], al[4];
#pragma unroll
            for (int half = 0; half < 2; half++) {
                const float* sv = S[2 * kt + half];
                split2h(sv[0], sv[1], ah[half * 2 + 0], al[half * 2 + 0]);
                split2h(sv[2], sv[3], ah[half * 2 + 1], al[half * 2 + 1]);
            }

            const int kb = kt * 32 + qc * 4;
#pragma unroll
            for (int nt = 0; nt < 8; nt++) {
                const char* vp = smb + KTILE + (nt * 8 + qr) * ATS + kb;
                uint32_t vf[2];
                vf[0] = *(const uint32_t*)vp;
                vf[1] = *(const uint32_t*)(vp + 16);
                mma16816(O[nt], ah, vf);
                mma16816(O[nt], al, vf);
            }
        }
    }

    // ---- finalize: normalize + fused fp16 split store ----
    l0 += __shfl_xor_sync(0xffffffffu, l0, 1);
    l0 += __shfl_xor_sync(0xffffffffu, l0, 2);
    l1 += __shfl_xor_sync(0xffffffffu, l1, 1);
    l1 += __shfl_xor_sync(0xffffffffu, l1, 2);
    const float inv0 = 1.f / l0, inv1 = 1.f / l1;

    const int s = s0 + wid * 16 + qr;
#pragma unroll
    for (int nt = 0; nt < 8; nt++) {
        const int col = h * DK + nt * 8 + qc * 2;
        const size_t i0 = ((size_t)(b * SEQ + s)    ) * DMODEL + col;
        const size_t i1 = ((size_t)(b * SEQ + s + 8)) * DMODEL + col;
        uint32_t hp, lp;
        split2h(O[nt][0] * inv0, O[nt][1] * inv0, hp, lp);
        *(uint32_t*)(Chi + i0) = hp;
        *(uint32_t*)(Clo + i0) = lp;
        split2h(O[nt][2] * inv1, O[nt][3] * inv1, hp, lp);
        *(uint32_t*)(Chi + i1) = hp;
        *(uint32_t*)(Clo + i1) = lp;
    }
}

// ---------------- launch ---------------------------------------------------
extern "C" void kernel_launch(void* const* d_in, const int* in_sizes, int n_in,
                              void* d_out, int out_size)
{
    (void)in_sizes; (void)n_in; (void)out_size;
    const float* q    = (const float*)d_in[0];
    const float* k    = (const float*)d_in[1];
    const float* v    = (const float*)d_in[2];
    const float* wq_w = (const float*)d_in[4];
    const float* wq_b = (const float*)d_in[5];
    const float* wk_w = (const float*)d_in[6];
    const float* wk_b = (const float*)d_in[7];
    const float* wv_w = (const float*)d_in[8];
    const float* wv_b = (const float*)d_in[9];
    const float* wo_w = (const float*)d_in[10];
    const float* wo_b = (const float*)d_in[11];
    float* out = (float*)d_out;

    __half *qhi, *qlo, *khi, *klo, *vhi, *vlo, *chi, *clo;
    __half *wqh, *wkh, *wvh, *woh;
    __half *qsh, *qsl, *ksh, *vth;
    cudaGetSymbolAddress((void**)&qhi, g_qhi);  cudaGetSymbolAddress((void**)&qlo, g_qlo);
    cudaGetSymbolAddress((void**)&khi, g_khi);  cudaGetSymbolAddress((void**)&klo, g_klo);
    cudaGetSymbolAddress((void**)&vhi, g_vhi);  cudaGetSymbolAddress((void**)&vlo, g_vlo);
    cudaGetSymbolAddress((void**)&chi, g_chi);  cudaGetSymbolAddress((void**)&clo, g_clo);
    cudaGetSymbolAddress((void**)&wqh, g_wqh);  cudaGetSymbolAddress((void**)&wkh, g_wkh);
    cudaGetSymbolAddress((void**)&wvh, g_wvh);  cudaGetSymbolAddress((void**)&woh, g_woh);
    cudaGetSymbolAddress((void**)&qsh, g_qsh);  cudaGetSymbolAddress((void**)&qsl, g_qsl);
    cudaGetSymbolAddress((void**)&ksh, g_ksh);  cudaGetSymbolAddress((void**)&vth, g_vth);

    cudaFuncSetAttribute(gemm_mma<0>, cudaFuncAttributeMaxDynamicSharedMemorySize, GEMM_SMEM);
    cudaFuncSetAttribute(gemm_mma<1>, cudaFuncAttributeMaxDynamicSharedMemorySize, GEMM_SMEM);
    cudaFuncSetAttribute(gemm_mma<2>, cudaFuncAttributeMaxDynamicSharedMemorySize, GEMM_SMEM);
    cudaFuncSetAttribute(gemm_mma<3>, cudaFuncAttributeMaxDynamicSharedMemorySize, GEMM_SMEM);
    cudaFuncSetAttribute(flash_mma,   cudaFuncAttributeMaxDynamicSharedMemorySize, FLASH_SMEM);

    const int nAct4 = MROWS * DMODEL / 4;
    const int nW4   = DMODEL * DMODEL / 4;

    {
        dim3 ga((nAct4 + 255) / 256, 3);
        split_fp16_multi<<<ga, 256>>>(
            (const float4*)q, (uint2*)qhi, (uint2*)qlo,
            (const float4*)k, (uint2*)khi, (uint2*)klo,
            (const float4*)v, (uint2*)vhi, (uint2*)vlo,
            nullptr, nullptr, nullptr, nAct4);
        dim3 gw((nW4 + 255) / 256, 4);
        split_fp16_multi<<<gw, 256>>>(
            (const float4*)wq_w, (uint2*)wqh, nullptr,
            (const float4*)wk_w, (uint2*)wkh, nullptr,
            (const float4*)wv_w, (uint2*)wvh, nullptr,
            (const float4*)wo_w, (uint2*)woh, nullptr, nW4);
    }

    const float qscale = 0.125f * 1.4426950408889634f;

    dim3 ggrid(DMODEL / 128, MROWS / 128);   // (8, 32)
    gemm_mma<1><<<ggrid, 256, GEMM_SMEM>>>(qhi, qlo, wqh, wq_b, qscale,
                                           nullptr, qsh, qsl);
    gemm_mma<3><<<ggrid, 256, GEMM_SMEM>>>(khi, klo, wkh, wk_b, 1.0f,
                                           nullptr, ksh, nullptr);
    gemm_mma<2><<<ggrid, 256, GEMM_SMEM>>>(vhi, vlo, wvh, wv_b, 1.0f,
                                           nullptr, vth, nullptr);

    dim3 agrid(SEQ / 128, BH);               // (16, 32)
    flash_mma<<<agrid, 256, FLASH_SMEM>>>(qsh, qsl, ksh, vth, chi, clo);

    gemm_mma<0><<<ggrid, 256, GEMM_SMEM>>>(chi, clo, woh, wo_b, 1.0f,
                                           out, nullptr, nullptr);
}

// round 15
// speedup vs baseline: 1.9690x; 1.0069x over previous
#include <cuda_runtime.h>
#include <cuda_bf16.h>
#include <cuda_fp16.h>
#include <cstdint>

// Problem constants
#define DMODEL 1024
#define HEADS  16
#define DK     64
#define BATCH  2
#define SEQ    2048
#define MROWS  (BATCH * SEQ)          // 4096
#define BH     (BATCH * HEADS)        // 32

// ---------------- scratch (static device memory; no allocs) ----------------
__device__ __half g_qhi[MROWS * DMODEL], g_qlo[MROWS * DMODEL];
__device__ __half g_khi[MROWS * DMODEL], g_klo[MROWS * DMODEL];
__device__ __half g_vhi[MROWS * DMODEL], g_vlo[MROWS * DMODEL];
__device__ __half g_chi[MROWS * DMODEL], g_clo[MROWS * DMODEL];
__device__ __half g_wqh[DMODEL * DMODEL];
__device__ __half g_wkh[DMODEL * DMODEL];
__device__ __half g_wvh[DMODEL * DMODEL];
__device__ __half g_woh[DMODEL * DMODEL];
__device__ __half g_qsh[BH * SEQ * DK], g_qsl[BH * SEQ * DK]; // Q split [bh][s][dk]
__device__ __half g_ksh[BH * SEQ * DK];                        // K single [bh][s][dk]
__device__ __half g_vth[BH * DK * SEQ];                        // V single [bh][dk][s]

// ---------------- helpers ---------------------------------------------------
__device__ __forceinline__ void mma16816(float* c, const uint32_t* a, const uint32_t* b) {
    asm volatile(
        "mma.sync.aligned.m16n8k16.row.col.f32.f16.f16.f32 "
        "{%0,%1,%2,%3}, {%4,%5,%6,%7}, {%8,%9}, {%0,%1,%2,%3};"
        : "+f"(c[0]), "+f"(c[1]), "+f"(c[2]), "+f"(c[3])
        : "r"(a[0]), "r"(a[1]), "r"(a[2]), "r"(a[3]), "r"(b[0]), "r"(b[1]));
}
__device__ __forceinline__ void ldsm4(uint32_t* r, uint32_t addr) {
    asm volatile("ldmatrix.sync.aligned.m8n8.x4.shared.b16 {%0,%1,%2,%3}, [%4];"
        : "=r"(r[0]), "=r"(r[1]), "=r"(r[2]), "=r"(r[3]) : "r"(addr));
}
__device__ __forceinline__ uint32_t smem_u32(const void* p) {
    uint32_t a;
    asm("{ .reg .u64 t; cvta.to.shared.u64 t, %1; cvt.u32.u64 %0, t; }"
        : "=r"(a) : "l"(p));
    return a;
}
__device__ __forceinline__ void cpa16(uint32_t dst, const void* src) {
    asm volatile("cp.async.cg.shared.global [%0], [%1], 16;" :: "r"(dst), "l"(src));
}
__device__ __forceinline__ void cpa_commit() {
    asm volatile("cp.async.commit_group;" ::: "memory");
}
template <int N>
__device__ __forceinline__ void cpa_wait() {
    asm volatile("cp.async.wait_group %0;" :: "n"(N) : "memory");
}
__device__ __forceinline__ float ex2f(float x) {
    float y; asm("ex2.approx.ftz.f32 %0, %1;" : "=f"(y) : "f"(x)); return y;
}
__device__ __forceinline__ uint32_t packh2(__half a, __half b) {
    __half2 t = __halves2half2(a, b);
    return *reinterpret_cast<uint32_t*>(&t);
}
__device__ __forceinline__ void split2h(float a, float b, uint32_t& hi, uint32_t& lo) {
    __half ha = __float2half_rn(a);
    __half hb = __float2half_rn(b);
    hi = packh2(ha, hb);
    lo = packh2(__float2half_rn(a - __half2float(ha)),
                __float2half_rn(b - __half2float(hb)));
}

// ---------------- fp32 -> fp16 split / convert (batched up to 4 tensors) ---
__global__ __launch_bounds__(256) void split_fp16_multi(
    const float4* __restrict__ x0, uint2* __restrict__ h0, uint2* __restrict__ l0,
    const float4* __restrict__ x1, uint2* __restrict__ h1, uint2* __restrict__ l1,
    const float4* __restrict__ x2, uint2* __restrict__ h2, uint2* __restrict__ l2,
    const float4* __restrict__ x3, uint2* __restrict__ h3, uint2* __restrict__ l3,
    int n4)
{
    const int sel = blockIdx.y;
    const float4* x = (sel == 0) ? x0 : (sel == 1) ? x1 : (sel == 2) ? x2 : x3;
    uint2* hi = (sel == 0) ? h0 : (sel == 1) ? h1 : (sel == 2) ? h2 : h3;
    uint2* lo = (sel == 0) ? l0 : (sel == 1) ? l1 : (sel == 2) ? l2 : l3;
    if (x == nullptr) return;

    int i = blockIdx.x * blockDim.x + threadIdx.x;
    if (i >= n4) return;
    float4 v = x[i];
    if (lo != nullptr) {
        uint32_t h01, l01, h23, l23;
        split2h(v.x, v.y, h01, l01);
        split2h(v.z, v.w, h23, l23);
        hi[i] = make_uint2(h01, h23);
        lo[i] = make_uint2(l01, l23);
    } else {
        hi[i] = make_uint2(packh2(__float2half_rn(v.x), __float2half_rn(v.y)),
                           packh2(__float2half_rn(v.z), __float2half_rn(v.w)));
    }
}

// ---------------- fp16 2-product GEMM: Y = (X @ W^T + bias) * scale --------
// X split (Ah+Al), W single (Bh):  acc = Ah*Bh + Al*Bh.
// 128x128 tile, warp 32(M)x64(N), BK=32, 80B rows (proven conflict-free).
// *** 3-stage cp.async pipeline, ONE barrier per chunk, 2 CTAs/SM ***
// (R9's barrier structure + R10's occupancy; fits now: 3 x 30720 = 92KB/CTA).
#define TSTRIDE   80
#define TILE_B    (128 * TSTRIDE)      // 10240
#define GBUF      (3 * TILE_B)         // Ah|Al|Bh = 30720
#define GEMM_SMEM (3 * GBUF)           // 92160 -> 2 CTAs/SM (184KB < 228KB)
#define NCHUNK    32

template <int MODE>
__global__ __launch_bounds__(256, 2) void gemm_mma(
    const __half* __restrict__ Ah, const __half* __restrict__ Al,
    const __half* __restrict__ Bh,
    const float* __restrict__ bias, float scale,
    float* __restrict__ Yf,
    __half* __restrict__ Yh, __half* __restrict__ Yl)
{
    extern __shared__ __align__(16) char smem_raw[];
    const uint32_t sb = smem_u32(smem_raw);

    const int tid  = threadIdx.x;
    const int wid  = tid >> 5, lane = tid & 31;
    const int wm   = wid & 3;            // 4 warps along M (32 each)
    const int wn   = wid >> 2;           // 2 warps along N (64 each)
    const int qr   = lane >> 2;
    const int qc   = lane & 3;
    const int row0 = blockIdx.y * 128;
    const int col0 = blockIdx.x * 128;

    const int lrow = (lane & 7) + ((lane >> 3) & 1) * 8;
    const int lbyt = (lane >> 4) * 16;

    float acc[2][8][4];
#pragma unroll
    for (int a = 0; a < 2; a++)
#pragma unroll
        for (int b = 0; b < 8; b++)
#pragma unroll
            for (int c = 0; c < 4; c++) acc[a][b][c] = 0.f;

    // 1536 x 16B transfers per chunk -> 6 per thread
    auto cpa_chunk = [&](int c, int buf) {
        const uint32_t db = sb + buf * GBUF;
#pragma unroll
        for (int i = 0; i < 6; i++) {
            const int u   = tid + i * 256;
            const int arr = u >> 9;            // 0=Ah 1=Al 2=Bh
            const int r   = (u & 511) >> 2;
            const int ch  = u & 3;
            const __half* src = (arr == 0) ? Ah : (arr == 1) ? Al : Bh;
            const int grow = ((arr < 2) ? row0 : col0) + r;
            cpa16(db + arr * TILE_B + r * TSTRIDE + ch * 16,
                  src + (size_t)grow * DMODEL + c * 32 + ch * 8);
        }
        cpa_commit();
    };

    cpa_chunk(0, 0);
    cpa_chunk(1, 1);

#pragma unroll 1
    for (int c = 0; c < NCHUNK; c++) {
        if (c == NCHUNK - 1) cpa_wait<0>(); else cpa_wait<1>();
        __syncthreads();                  // chunk c visible; all warps done c-1
        if (c + 2 < NCHUNK) cpa_chunk(c + 2, (c + 2) % 3);

        const uint32_t bb = sb + (c % 3) * GBUF;
#pragma unroll
        for (int ks = 0; ks < 2; ks++) {
            const int kb = ks * 32 + lbyt;

            uint32_t bf[8][2];
#pragma unroll
            for (int half = 0; half < 4; half++) {
                const uint32_t addr = bb + 2 * TILE_B
                    + (wn * 64 + half * 16 + lrow) * TSTRIDE + kb;
                uint32_t th[4];
                ldsm4(th, addr);
                bf[half * 2 + 0][0] = th[0]; bf[half * 2 + 1][0] = th[1];
                bf[half * 2 + 0][1] = th[2]; bf[half * 2 + 1][1] = th[3];
            }
#pragma unroll
            for (int mt = 0; mt < 2; mt++) {
                const uint32_t addr = bb + (wm * 32 + mt * 16 + lrow) * TSTRIDE + kb;
                uint32_t ah[4], al[4];
                ldsm4(ah, addr);
                ldsm4(al, addr + TILE_B);
#pragma unroll
                for (int nt = 0; nt < 8; nt++) {
                    mma16816(acc[mt][nt], ah, bf[nt]);
                    mma16816(acc[mt][nt], al, bf[nt]);
                }
            }
        }
    }

    // ---- epilogue ----
#pragma unroll
    for (int mt = 0; mt < 2; mt++) {
#pragma unroll
        for (int nt = 0; nt < 8; nt++) {
            const int col = col0 + wn * 64 + nt * 8 + qc * 2;
            float2 bv = *(const float2*)&bias[col];
#pragma unroll
            for (int h = 0; h < 2; h++) {
                const int m = row0 + wm * 32 + mt * 16 + qr + h * 8;
                float v0 = (acc[mt][nt][h * 2 + 0] + bv.x) * scale;
                float v1 = (acc[mt][nt][h * 2 + 1] + bv.y) * scale;
                if (MODE == 0) {
                    float2 r; r.x = v0; r.y = v1;
                    *(float2*)(Yf + (size_t)m * DMODEL + col) = r;
                } else {
                    const int b  = m >> 11, s = m & (SEQ - 1);
                    const int hh = col >> 6, dk = col & 63;
                    if (MODE == 1) {           // Q: split fp16
                        uint32_t hp, lp;
                        split2h(v0, v1, hp, lp);
                        const size_t idx = ((size_t)(b * HEADS + hh) * SEQ + s) * DK + dk;
                        *(uint32_t*)(Yh + idx) = hp;
                        *(uint32_t*)(Yl + idx) = lp;
                    } else if (MODE == 3) {    // K: single fp16
                        const size_t idx = ((size_t)(b * HEADS + hh) * SEQ + s) * DK + dk;
                        *(uint32_t*)(Yh + idx) =
                            packh2(__float2half_rn(v0), __float2half_rn(v1));
                    } else {                   // MODE 2: V single fp16, [bh][dk][s]
                        const size_t base = ((size_t)(b * HEADS + hh) * DK + dk) * SEQ + s;
                        Yh[base]       = __float2half_rn(v0);
                        Yh[base + SEQ] = __float2half_rn(v1);
                    }
                }
            }
        }
    }
}

// ---------------- fp16 2-product flash attention (unchanged from R14) ------
#define ATS    144
#define KTILE  (64 * ATS)              // 9216
#define QTILE  (128 * ATS)             // 18432
#define FBUF   (2 * KTILE)             // Kh|Vth = 18432
#define FLASH_SMEM (3 * FBUF)          // 55296 (>= 2*QTILE for Q staging)
#define NT     (SEQ / 64)              // 32

__global__ __launch_bounds__(256) void flash_mma(
    const __half* __restrict__ Qh, const __half* __restrict__ Ql,
    const __half* __restrict__ Kh, const __half* __restrict__ Vth,
    __half* __restrict__ Chi, __half* __restrict__ Clo)
{
    extern __shared__ __align__(16) char sm[];
    const uint32_t sbf = smem_u32(sm);

    const int tid = threadIdx.x, wid = tid >> 5, lane = tid & 31;
    const int qr = lane >> 2, qc = lane & 3;
    const int bh = blockIdx.y;
    const int s0 = blockIdx.x * 128;
    const int b  = bh >> 4, h = bh & 15;

    // ---- stage Q tile (qh at 0, ql at QTILE), extract A-fragments ----
#pragma unroll
    for (int i = 0; i < 8; i++) {
        int u = tid + i * 256;          // 0..2047
        int arr = u >> 10;              // 0=hi 1=lo
        int idx = u & 1023, r = idx >> 3, ch = idx & 7;
        const __half* src = arr ? Ql : Qh;
        *(float4*)(sm + arr * QTILE + r * ATS + ch * 16) =
            *(const float4*)(src + ((size_t)bh * SEQ + s0 + r) * DK + ch * 8);
    }
    __syncthreads();
    uint32_t qfh[4][4], qfl[4][4];
    {
        const char* base = sm + (wid * 16 + qr) * ATS;
#pragma unroll
        for (int kt = 0; kt < 4; kt++) {
            const int off = kt * 32 + qc * 4;
            qfh[kt][0] = *(const uint32_t*)(base + off);
            qfh[kt][1] = *(const uint32_t*)(base + 8 * ATS + off);
            qfh[kt][2] = *(const uint32_t*)(base + off + 16);
            qfh[kt][3] = *(const uint32_t*)(base + 8 * ATS + off + 16);
            qfl[kt][0] = *(const uint32_t*)(base + QTILE + off);
            qfl[kt][1] = *(const uint32_t*)(base + QTILE + 8 * ATS + off);
            qfl[kt][2] = *(const uint32_t*)(base + QTILE + off + 16);
            qfl[kt][3] = *(const uint32_t*)(base + QTILE + 8 * ATS + off + 16);
        }
    }
    __syncthreads();                    // Q fully consumed before buffer reuse

    float O[8][4];
#pragma unroll
    for (int nt = 0; nt < 8; nt++)
#pragma unroll
        for (int c = 0; c < 4; c++) O[nt][c] = 0.f;
    float m0 = -1e30f, m1 = -1e30f, l0 = 0.f, l1 = 0.f;

    auto cpaKV = [&](int t, int buf) {
        const uint32_t db = sbf + buf * FBUF;
        const int j0 = t * 64;
#pragma unroll
        for (int i = 0; i < 4; i++) {
            int u = tid + i * 256;
            int arr = u >> 9;           // 0=Kh 1=Vth
            int idx = u & 511, r = idx >> 3, ch = idx & 7;
            const __half* src = arr ? Vth : Kh;
            size_t g = (arr == 0)
                ? (((size_t)bh * SEQ + j0 + r) * DK + ch * 8)
                : (((size_t)bh * DK + r) * SEQ + j0 + ch * 8);
            cpa16(db + arr * KTILE + r * ATS + ch * 16, src + g);
        }
        cpa_commit();
    };

    cpaKV(0, 0);
    cpaKV(1, 1);

#pragma unroll 1
    for (int t = 0; t < NT; t++) {
        if (t == NT - 1) cpa_wait<0>(); else cpa_wait<1>();
        __syncthreads();
        if (t + 2 < NT) cpaKV(t + 2, (t + 2) % 3);
        const char* smb = sm + (t % 3) * FBUF;

        // ---- S = Q K^T (2-product fp16), base-2 domain ----
        float S[8][4];
#pragma unroll
        for (int nt = 0; nt < 8; nt++)
#pragma unroll
            for (int c = 0; c < 4; c++) S[nt][c] = 0.f;

#pragma unroll
        for (int kt = 0; kt < 4; kt++) {
            const int kb = kt * 32 + qc * 4;
#pragma unroll
            for (int nt = 0; nt < 8; nt++) {
                const char* kp = smb + (nt * 8 + qr) * ATS + kb;
                uint32_t kf[2];
                kf[0] = *(const uint32_t*)kp;
                kf[1] = *(const uint32_t*)(kp + 16);
                mma16816(S[nt], qfh[kt], kf);
                mma16816(S[nt], qfl[kt], kf);
            }
        }

        // ---- online softmax (base 2) ----
        float rx0 = -1e30f, rx1 = -1e30f;
#pragma unroll
        for (int nt = 0; nt < 8; nt++) {
            rx0 = fmaxf(rx0, fmaxf(S[nt][0], S[nt][1]));
            rx1 = fmaxf(rx1, fmaxf(S[nt][2], S[nt][3]));
        }
        rx0 = fmaxf(rx0, __shfl_xor_sync(0xffffffffu, rx0, 1));
        rx0 = fmaxf(rx0, __shfl_xor_sync(0xffffffffu, rx0, 2));
        rx1 = fmaxf(rx1, __shfl_xor_sync(0xffffffffu, rx1, 1));
        rx1 = fmaxf(rx1, __shfl_xor_sync(0xffffffffu, rx1, 2));

        const float mn0 = fmaxf(m0, rx0);
        const float mn1 = fmaxf(m1, rx1);
        const float a0 = ex2f(m0 - mn0);
        const float a1 = ex2f(m1 - mn1);
        m0 = mn0; m1 = mn1;
        l0 *= a0;  l1 *= a1;

#pragma unroll
        for (int nt = 0; nt < 8; nt++) {
            S[nt][0] = ex2f(S[nt][0] - m0);
            S[nt][1] = ex2f(S[nt][1] - m0);
            S[nt][2] = ex2f(S[nt][2] - m1);
            S[nt][3] = ex2f(S[nt][3] - m1);
            l0 += S[nt][0] + S[nt][1];
            l1 += S[nt][2] + S[nt][3];
            O[nt][0] *= a0; O[nt][1] *= a0;
            O[nt][2] *= a1; O[nt][3] *= a1;
        }

        // ---- O += P V (P split fp16 in registers, V single) ----
#pragma unroll
        for (int kt = 0; kt < 4; kt++) {
            uint32_t ah[4], al[4];
#pragma unroll
            for (int half = 0; half < 2; half++) {
                const float* sv = S[2 * kt + half];
                split2h(sv[0], sv[1], ah[half * 2 + 0], al[half * 2 + 0]);
                split2h(sv[2], sv[3], ah[half * 2 + 1], al[half * 2 + 1]);
            }

            const int kb = kt * 32 + qc * 4;
#pragma unroll
            for (int nt = 0; nt < 8; nt++) {
                const char* vp = smb + KTILE + (nt * 8 + qr) * ATS + kb;
                uint32_t vf[2];
                vf[0] = *(const uint32_t*)vp;
                vf[1] = *(const uint32_t*)(vp + 16);
                mma16816(O[nt], ah, vf);
                mma16816(O[nt], al, vf);
            }
        }
    }

    // ---- finalize: normalize + fused fp16 split store ----
    l0 += __shfl_xor_sync(0xffffffffu, l0, 1);
    l0 += __shfl_xor_sync(0xffffffffu, l0, 2);
    l1 += __shfl_xor_sync(0xffffffffu, l1, 1);
    l1 += __shfl_xor_sync(0xffffffffu, l1, 2);
    const float inv0 = 1.f / l0, inv1 = 1.f / l1;

    const int s = s0 + wid * 16 + qr;
#pragma unroll
    for (int nt = 0; nt < 8; nt++) {
        const int col = h * DK + nt * 8 + qc * 2;
        const size_t i0 = ((size_t)(b * SEQ + s)    ) * DMODEL + col;
        const size_t i1 = ((size_t)(b * SEQ + s + 8)) * DMODEL + col;
        uint32_t hp, lp;
        split2h(O[nt][0] * inv0, O[nt][1] * inv0, hp, lp);
        *(uint32_t*)(Chi + i0) = hp;
        *(uint32_t*)(Clo + i0) = lp;
        split2h(O[nt][2] * inv1, O[nt][3] * inv1, hp, lp);
        *(uint32_t*)(Chi + i1) = hp;
        *(uint32_t*)(Clo + i1) = lp;
    }
}

// ---------------- launch ---------------------------------------------------
extern "C" void kernel_launch(void* const* d_in, const int* in_sizes, int n_in,
                              void* d_out, int out_size)
{
    (void)in_sizes; (void)n_in; (void)out_size;
    const float* q    = (const float*)d_in[0];
    const float* k    = (const float*)d_in[1];
    const float* v    = (const float*)d_in[2];
    const float* wq_w = (const float*)d_in[4];
    const float* wq_b = (const float*)d_in[5];
    const float* wk_w = (const float*)d_in[6];
    const float* wk_b = (const float*)d_in[7];
    const float* wv_w = (const float*)d_in[8];
    const float* wv_b = (const float*)d_in[9];
    const float* wo_w = (const float*)d_in[10];
    const float* wo_b = (const float*)d_in[11];
    float* out = (float*)d_out;

    __half *qhi, *qlo, *khi, *klo, *vhi, *vlo, *chi, *clo;
    __half *wqh, *wkh, *wvh, *woh;
    __half *qsh, *qsl, *ksh, *vth;
    cudaGetSymbolAddress((void**)&qhi, g_qhi);  cudaGetSymbolAddress((void**)&qlo, g_qlo);
    cudaGetSymbolAddress((void**)&khi, g_khi);  cudaGetSymbolAddress((void**)&klo, g_klo);
    cudaGetSymbolAddress((void**)&vhi, g_vhi);  cudaGetSymbolAddress((void**)&vlo, g_vlo);
    cudaGetSymbolAddress((void**)&chi, g_chi);  cudaGetSymbolAddress((void**)&clo, g_clo);
    cudaGetSymbolAddress((void**)&wqh, g_wqh);  cudaGetSymbolAddress((void**)&wkh, g_wkh);
    cudaGetSymbolAddress((void**)&wvh, g_wvh);  cudaGetSymbolAddress((void**)&woh, g_woh);
    cudaGetSymbolAddress((void**)&qsh, g_qsh);  cudaGetSymbolAddress((void**)&qsl, g_qsl);
    cudaGetSymbolAddress((void**)&ksh, g_ksh);  cudaGetSymbolAddress((void**)&vth, g_vth);

    cudaFuncSetAttribute(gemm_mma<0>, cudaFuncAttributeMaxDynamicSharedMemorySize, GEMM_SMEM);
    cudaFuncSetAttribute(gemm_mma<1>, cudaFuncAttributeMaxDynamicSharedMemorySize, GEMM_SMEM);
    cudaFuncSetAttribute(gemm_mma<2>, cudaFuncAttributeMaxDynamicSharedMemorySize, GEMM_SMEM);
    cudaFuncSetAttribute(gemm_mma<3>, cudaFuncAttributeMaxDynamicSharedMemorySize, GEMM_SMEM);
    cudaFuncSetAttribute(flash_mma,   cudaFuncAttributeMaxDynamicSharedMemorySize, FLASH_SMEM);

    const int nAct4 = MROWS * DMODEL / 4;
    const int nW4   = DMODEL * DMODEL / 4;

    {
        dim3 ga((nAct4 + 255) / 256, 3);
        split_fp16_multi<<<ga, 256>>>(
            (const float4*)q, (uint2*)qhi, (uint2*)qlo,
            (const float4*)k, (uint2*)khi, (uint2*)klo,
            (const float4*)v, (uint2*)vhi, (uint2*)vlo,
            nullptr, nullptr, nullptr, nAct4);
        dim3 gw((nW4 + 255) / 256, 4);
        split_fp16_multi<<<gw, 256>>>(
            (const float4*)wq_w, (uint2*)wqh, nullptr,
            (const float4*)wk_w, (uint2*)wkh, nullptr,
            (const float4*)wv_w, (uint2*)wvh, nullptr,
            (const float4*)wo_w, (uint2*)woh, nullptr, nW4);
    }

    const float qscale = 0.125f * 1.4426950408889634f;

    dim3 ggrid(DMODEL / 128, MROWS / 128);   // (8, 32)
    gemm_mma<1><<<ggrid, 256, GEMM_SMEM>>>(qhi, qlo, wqh, wq_b, qscale,
                                           nullptr, qsh, qsl);
    gemm_mma<3><<<ggrid, 256, GEMM_SMEM>>>(khi, klo, wkh, wk_b, 1.0f,
                                           nullptr, ksh, nullptr);
    gemm_mma<2><<<ggrid, 256, GEMM_SMEM>>>(vhi, vlo, wvh, wv_b, 1.0f,
                                           nullptr, vth, nullptr);

    dim3 agrid(SEQ / 128, BH);               // (16, 32)
    flash_mma<<<agrid, 256, FLASH_SMEM>>>(qsh, qsl, ksh, vth, chi, clo);

    gemm_mma<0><<<ggrid, 256, GEMM_SMEM>>>(chi, clo, woh, wo_b, 1.0f,
                                           out, nullptr, nullptr);
}

// round 16
// speedup vs baseline: 2.1105x; 1.0719x over previous
#include <cuda_runtime.h>
#include <cuda_bf16.h>
#include <cuda_fp16.h>
#include <cstdint>

// Problem constants
#define DMODEL 1024
#define HEADS  16
#define DK     64
#define BATCH  2
#define SEQ    2048
#define MROWS  (BATCH * SEQ)          // 4096
#define BH     (BATCH * HEADS)        // 32

// ---------------- scratch (static device memory; no allocs) ----------------
__device__ __half g_qhi[MROWS * DMODEL], g_qlo[MROWS * DMODEL];
__device__ __half g_khi[MROWS * DMODEL], g_klo[MROWS * DMODEL];
__device__ __half g_vhi[MROWS * DMODEL], g_vlo[MROWS * DMODEL];
__device__ __half g_chi[MROWS * DMODEL], g_clo[MROWS * DMODEL];
__device__ __half g_wqh[DMODEL * DMODEL];
__device__ __half g_wkh[DMODEL * DMODEL];
__device__ __half g_wvh[DMODEL * DMODEL];
__device__ __half g_woh[DMODEL * DMODEL];
__device__ __half g_qsh[BH * SEQ * DK], g_qsl[BH * SEQ * DK]; // Q split [bh][s][dk]
__device__ __half g_ksh[BH * SEQ * DK];                        // K single [bh][s][dk]
__device__ __half g_vth[BH * DK * SEQ];                        // V single [bh][dk][s]

// ---------------- helpers ---------------------------------------------------
__device__ __forceinline__ void mma16816(float* c, const uint32_t* a, const uint32_t* b) {
    asm volatile(
        "mma.sync.aligned.m16n8k16.row.col.f32.f16.f16.f32 "
        "{%0,%1,%2,%3}, {%4,%5,%6,%7}, {%8,%9}, {%0,%1,%2,%3};"
        : "+f"(c[0]), "+f"(c[1]), "+f"(c[2]), "+f"(c[3])
        : "r"(a[0]), "r"(a[1]), "r"(a[2]), "r"(a[3]), "r"(b[0]), "r"(b[1]));
}
__device__ __forceinline__ void ldsm4(uint32_t* r, uint32_t addr) {
    asm volatile("ldmatrix.sync.aligned.m8n8.x4.shared.b16 {%0,%1,%2,%3}, [%4];"
        : "=r"(r[0]), "=r"(r[1]), "=r"(r[2]), "=r"(r[3]) : "r"(addr));
}
__device__ __forceinline__ uint32_t smem_u32(const void* p) {
    uint32_t a;
    asm("{ .reg .u64 t; cvta.to.shared.u64 t, %1; cvt.u32.u64 %0, t; }"
        : "=r"(a) : "l"(p));
    return a;
}
__device__ __forceinline__ void cpa16(uint32_t dst, const void* src) {
    asm volatile("cp.async.cg.shared.global [%0], [%1], 16;" :: "r"(dst), "l"(src));
}
__device__ __forceinline__ void cpa_commit() {
    asm volatile("cp.async.commit_group;" ::: "memory");
}
template <int N>
__device__ __forceinline__ void cpa_wait() {
    asm volatile("cp.async.wait_group %0;" :: "n"(N) : "memory");
}
__device__ __forceinline__ float ex2f(float x) {
    float y; asm("ex2.approx.ftz.f32 %0, %1;" : "=f"(y) : "f"(x)); return y;
}
__device__ __forceinline__ uint32_t packh2(__half a, __half b) {
    __half2 t = __halves2half2(a, b);
    return *reinterpret_cast<uint32_t*>(&t);
}
__device__ __forceinline__ void split2h(float a, float b, uint32_t& hi, uint32_t& lo) {
    __half ha = __float2half_rn(a);
    __half hb = __float2half_rn(b);
    hi = packh2(ha, hb);
    lo = packh2(__float2half_rn(a - __half2float(ha)),
                __float2half_rn(b - __half2float(hb)));
}

// ---------------- fp32 -> fp16 split / convert (batched up to 4 tensors) ---
__global__ __launch_bounds__(256) void split_fp16_multi(
    const float4* __restrict__ x0, uint2* __restrict__ h0, uint2* __restrict__ l0,
    const float4* __restrict__ x1, uint2* __restrict__ h1, uint2* __restrict__ l1,
    const float4* __restrict__ x2, uint2* __restrict__ h2, uint2* __restrict__ l2,
    const float4* __restrict__ x3, uint2* __restrict__ h3, uint2* __restrict__ l3,
    int n4)
{
    const int sel = blockIdx.y;
    const float4* x = (sel == 0) ? x0 : (sel == 1) ? x1 : (sel == 2) ? x2 : x3;
    uint2* hi = (sel == 0) ? h0 : (sel == 1) ? h1 : (sel == 2) ? h2 : h3;
    uint2* lo = (sel == 0) ? l0 : (sel == 1) ? l1 : (sel == 2) ? l2 : l3;
    if (x == nullptr) return;

    int i = blockIdx.x * blockDim.x + threadIdx.x;
    if (i >= n4) return;
    float4 v = x[i];
    if (lo != nullptr) {
        uint32_t h01, l01, h23, l23;
        split2h(v.x, v.y, h01, l01);
        split2h(v.z, v.w, h23, l23);
        hi[i] = make_uint2(h01, h23);
        lo[i] = make_uint2(l01, l23);
    } else {
        hi[i] = make_uint2(packh2(__float2half_rn(v.x), __float2half_rn(v.y)),
                           packh2(__float2half_rn(v.z), __float2half_rn(v.w)));
    }
}

// ---------------- fp16 2-product GEMM core (R15-proven mainloop) -----------
#define TSTRIDE   80
#define TILE_B    (128 * TSTRIDE)      // 10240
#define GBUF      (3 * TILE_B)         // Ah|Al|Bh = 30720
#define GEMM_SMEM (3 * GBUF)           // 92160 -> 2 CTAs/SM
#define NCHUNK    32

// mainloop shared by both GEMM kernels; computes warp-tile acc
struct GemmCtx {
    int tid, wid, lane, wm, wn, qr, qc, lrow, lbyt, row0, col0;
    uint32_t sb;
};

__device__ __forceinline__ void gemm_mainloop(
    const GemmCtx& g,
    const __half* __restrict__ Ah, const __half* __restrict__ Al,
    const __half* __restrict__ Bh, float acc[2][8][4])
{
#pragma unroll
    for (int a = 0; a < 2; a++)
#pragma unroll
        for (int b = 0; b < 8; b++)
#pragma unroll
            for (int c = 0; c < 4; c++) acc[a][b][c] = 0.f;

    auto cpa_chunk = [&](int c, int buf) {
        const uint32_t db = g.sb + buf * GBUF;
#pragma unroll
        for (int i = 0; i < 6; i++) {
            const int u   = g.tid + i * 256;
            const int arr = u >> 9;            // 0=Ah 1=Al 2=Bh
            const int r   = (u & 511) >> 2;
            const int ch  = u & 3;
            const __half* src = (arr == 0) ? Ah : (arr == 1) ? Al : Bh;
            const int grow = ((arr < 2) ? g.row0 : g.col0) + r;
            cpa16(db + arr * TILE_B + r * TSTRIDE + ch * 16,
                  src + (size_t)grow * DMODEL + c * 32 + ch * 8);
        }
        cpa_commit();
    };

    cpa_chunk(0, 0);
    cpa_chunk(1, 1);

#pragma unroll 1
    for (int c = 0; c < NCHUNK; c++) {
        if (c == NCHUNK - 1) cpa_wait<0>(); else cpa_wait<1>();
        __syncthreads();
        if (c + 2 < NCHUNK) cpa_chunk(c + 2, (c + 2) % 3);

        const uint32_t bb = g.sb + (c % 3) * GBUF;
#pragma unroll
        for (int ks = 0; ks < 2; ks++) {
            const int kb = ks * 32 + g.lbyt;

            uint32_t bf[8][2];
#pragma unroll
            for (int half = 0; half < 4; half++) {
                const uint32_t addr = bb + 2 * TILE_B
                    + (g.wn * 64 + half * 16 + g.lrow) * TSTRIDE + kb;
                uint32_t th[4];
                ldsm4(th, addr);
                bf[half * 2 + 0][0] = th[0]; bf[half * 2 + 1][0] = th[1];
                bf[half * 2 + 0][1] = th[2]; bf[half * 2 + 1][1] = th[3];
            }
#pragma unroll
            for (int mt = 0; mt < 2; mt++) {
                const uint32_t addr = bb + (g.wm * 32 + mt * 16 + g.lrow) * TSTRIDE + kb;
                uint32_t ah[4], al[4];
                ldsm4(ah, addr);
                ldsm4(al, addr + TILE_B);
#pragma unroll
                for (int nt = 0; nt < 8; nt++) {
                    mma16816(acc[mt][nt], ah, bf[nt]);
                    mma16816(acc[mt][nt], al, bf[nt]);
                }
            }
        }
    }
}

__device__ __forceinline__ GemmCtx make_ctx(uint32_t sb, int row0, int col0) {
    GemmCtx g;
    g.tid = threadIdx.x;
    g.wid = g.tid >> 5; g.lane = g.tid & 31;
    g.wm = g.wid & 3;   g.wn = g.wid >> 2;
    g.qr = g.lane >> 2; g.qc = g.lane & 3;
    g.lrow = (g.lane & 7) + ((g.lane >> 3) & 1) * 8;
    g.lbyt = (g.lane >> 4) * 16;
    g.row0 = row0; g.col0 = col0; g.sb = sb;
    return g;
}

// ---- fused QKV projection: blockIdx.z selects {Q, K, V} -------------------
__global__ __launch_bounds__(256, 2) void qkv_gemm(
    const __half* __restrict__ Aqh, const __half* __restrict__ Aql,
    const __half* __restrict__ Akh, const __half* __restrict__ Akl,
    const __half* __restrict__ Avh, const __half* __restrict__ Avl,
    const __half* __restrict__ Wq, const __half* __restrict__ Wk,
    const __half* __restrict__ Wv,
    const float* __restrict__ bq, const float* __restrict__ bk,
    const float* __restrict__ bv, float qscale,
    __half* __restrict__ Qh, __half* __restrict__ Ql,
    __half* __restrict__ Kh, __half* __restrict__ Vt)
{
    extern __shared__ __align__(16) char smem_raw[];
    const int z = blockIdx.z;
    const GemmCtx g = make_ctx(smem_u32(smem_raw),
                               blockIdx.y * 128, blockIdx.x * 128);

    const __half* Ah = (z == 0) ? Aqh : (z == 1) ? Akh : Avh;
    const __half* Al = (z == 0) ? Aql : (z == 1) ? Akl : Avl;
    const __half* Bh = (z == 0) ? Wq  : (z == 1) ? Wk  : Wv;
    const float* bias = (z == 0) ? bq : (z == 1) ? bk : bv;
    const float scale = (z == 0) ? qscale : 1.0f;

    float acc[2][8][4];
    gemm_mainloop(g, Ah, Al, Bh, acc);

    // ---- epilogue (per-z layout) ----
#pragma unroll
    for (int mt = 0; mt < 2; mt++) {
#pragma unroll
        for (int nt = 0; nt < 8; nt++) {
            const int col = g.col0 + g.wn * 64 + nt * 8 + g.qc * 2;
            float2 bv2 = *(const float2*)&bias[col];
#pragma unroll
            for (int h = 0; h < 2; h++) {
                const int m = g.row0 + g.wm * 32 + mt * 16 + g.qr + h * 8;
                float v0 = (acc[mt][nt][h * 2 + 0] + bv2.x) * scale;
                float v1 = (acc[mt][nt][h * 2 + 1] + bv2.y) * scale;
                const int b  = m >> 11, s = m & (SEQ - 1);
                const int hh = col >> 6, dk = col & 63;
                if (z == 0) {              // Q: split fp16
                    uint32_t hp, lp;
                    split2h(v0, v1, hp, lp);
                    const size_t idx = ((size_t)(b * HEADS + hh) * SEQ + s) * DK + dk;
                    *(uint32_t*)(Qh + idx) = hp;
                    *(uint32_t*)(Ql + idx) = lp;
                } else if (z == 1) {       // K: single fp16
                    const size_t idx = ((size_t)(b * HEADS + hh) * SEQ + s) * DK + dk;
                    *(uint32_t*)(Kh + idx) =
                        packh2(__float2half_rn(v0), __float2half_rn(v1));
                } else {                   // V: single fp16, [bh][dk][s]
                    const size_t base = ((size_t)(b * HEADS + hh) * DK + dk) * SEQ + s;
                    Vt[base]       = __float2half_rn(v0);
                    Vt[base + SEQ] = __float2half_rn(v1);
                }
            }
        }
    }
}

// ---- output projection: ctx(split) @ Wo + bias -> fp32 out ---------------
__global__ __launch_bounds__(256, 2) void out_gemm(
    const __half* __restrict__ Ah, const __half* __restrict__ Al,
    const __half* __restrict__ Bh,
    const float* __restrict__ bias, float* __restrict__ Yf)
{
    extern __shared__ __align__(16) char smem_raw[];
    const GemmCtx g = make_ctx(smem_u32(smem_raw),
                               blockIdx.y * 128, blockIdx.x * 128);

    float acc[2][8][4];
    gemm_mainloop(g, Ah, Al, Bh, acc);

#pragma unroll
    for (int mt = 0; mt < 2; mt++) {
#pragma unroll
        for (int nt = 0; nt < 8; nt++) {
            const int col = g.col0 + g.wn * 64 + nt * 8 + g.qc * 2;
            float2 bv2 = *(const float2*)&bias[col];
#pragma unroll
            for (int h = 0; h < 2; h++) {
                const int m = g.row0 + g.wm * 32 + mt * 16 + g.qr + h * 8;
                float2 r;
                r.x = acc[mt][nt][h * 2 + 0] + bv2.x;
                r.y = acc[mt][nt][h * 2 + 1] + bv2.y;
                *(float2*)(Yf + (size_t)m * DMODEL + col) = r;
            }
        }
    }
}

// ---------------- fp16 2-product flash attention (R15 + occ 2 cap) ---------
#define ATS    144
#define KTILE  (64 * ATS)              // 9216
#define QTILE  (128 * ATS)             // 18432
#define FBUF   (2 * KTILE)             // Kh|Vth = 18432
#define FLASH_SMEM (3 * FBUF)          // 55296 -> 2 CTAs/SM
#define NT     (SEQ / 64)              // 32

__global__ __launch_bounds__(256, 2) void flash_mma(
    const __half* __restrict__ Qh, const __half* __restrict__ Ql,
    const __half* __restrict__ Kh, const __half* __restrict__ Vth,
    __half* __restrict__ Chi, __half* __restrict__ Clo)
{
    extern __shared__ __align__(16) char sm[];
    const uint32_t sbf = smem_u32(sm);

    const int tid = threadIdx.x, wid = tid >> 5, lane = tid & 31;
    const int qr = lane >> 2, qc = lane & 3;
    const int bh = blockIdx.y;
    const int s0 = blockIdx.x * 128;
    const int b  = bh >> 4, h = bh & 15;

    // ---- stage Q tile (qh at 0, ql at QTILE), extract A-fragments ----
#pragma unroll
    for (int i = 0; i < 8; i++) {
        int u = tid + i * 256;          // 0..2047
        int arr = u >> 10;              // 0=hi 1=lo
        int idx = u & 1023, r = idx >> 3, ch = idx & 7;
        const __half* src = arr ? Ql : Qh;
        *(float4*)(sm + arr * QTILE + r * ATS + ch * 16) =
            *(const float4*)(src + ((size_t)bh * SEQ + s0 + r) * DK + ch * 8);
    }
    __syncthreads();
    uint32_t qfh[4][4], qfl[4][4];
    {
        const char* base = sm + (wid * 16 + qr) * ATS;
#pragma unroll
        for (int kt = 0; kt < 4; kt++) {
            const int off = kt * 32 + qc * 4;
            qfh[kt][0] = *(const uint32_t*)(base + off);
            qfh[kt][1] = *(const uint32_t*)(base + 8 * ATS + off);
            qfh[kt][2] = *(const uint32_t*)(base + off + 16);
            qfh[kt][3] = *(const uint32_t*)(base + 8 * ATS + off + 16);
            qfl[kt][0] = *(const uint32_t*)(base + QTILE + off);
            qfl[kt][1] = *(const uint32_t*)(base + QTILE + 8 * ATS + off);
            qfl[kt][2] = *(const uint32_t*)(base + QTILE + off + 16);
            qfl[kt][3] = *(const uint32_t*)(base + QTILE + 8 * ATS + off + 16);
        }
    }
    __syncthreads();                    // Q fully consumed before buffer reuse

    float O[8][4];
#pragma unroll
    for (int nt = 0; nt < 8; nt++)
#pragma unroll
        for (int c = 0; c < 4; c++) O[nt][c] = 0.f;
    float m0 = -1e30f, m1 = -1e30f, l0 = 0.f, l1 = 0.f;

    auto cpaKV = [&](int t, int buf) {
        const uint32_t db = sbf + buf * FBUF;
        const int j0 = t * 64;
#pragma unroll
        for (int i = 0; i < 4; i++) {
            int u = tid + i * 256;
            int arr = u >> 9;           // 0=Kh 1=Vth
            int idx = u & 511, r = idx >> 3, ch = idx & 7;
            const __half* src = arr ? Vth : Kh;
            size_t g = (arr == 0)
                ? (((size_t)bh * SEQ + j0 + r) * DK + ch * 8)
                : (((size_t)bh * DK + r) * SEQ + j0 + ch * 8);
            cpa16(db + arr * KTILE + r * ATS + ch * 16, src + g);
        }
        cpa_commit();
    };

    cpaKV(0, 0);
    cpaKV(1, 1);

#pragma unroll 1
    for (int t = 0; t < NT; t++) {
        if (t == NT - 1) cpa_wait<0>(); else cpa_wait<1>();
        __syncthreads();
        if (t + 2 < NT) cpaKV(t + 2, (t + 2) % 3);
        const char* smb = sm + (t % 3) * FBUF;

        // ---- S = Q K^T (2-product fp16), base-2 domain ----
        float S[8][4];
#pragma unroll
        for (int nt = 0; nt < 8; nt++)
#pragma unroll
            for (int c = 0; c < 4; c++) S[nt][c] = 0.f;

#pragma unroll
        for (int kt = 0; kt < 4; kt++) {
            const int kb = kt * 32 + qc * 4;
#pragma unroll
            for (int nt = 0; nt < 8; nt++) {
                const char* kp = smb + (nt * 8 + qr) * ATS + kb;
                uint32_t kf[2];
                kf[0] = *(const uint32_t*)kp;
                kf[1] = *(const uint32_t*)(kp + 16);
                mma16816(S[nt], qfh[kt], kf);
                mma16816(S[nt], qfl[kt], kf);
            }
        }

        // ---- online softmax (base 2) ----
        float rx0 = -1e30f, rx1 = -1e30f;
#pragma unroll
        for (int nt = 0; nt < 8; nt++) {
            rx0 = fmaxf(rx0, fmaxf(S[nt][0], S[nt][1]));
            rx1 = fmaxf(rx1, fmaxf(S[nt][2], S[nt][3]));
        }
        rx0 = fmaxf(rx0, __shfl_xor_sync(0xffffffffu, rx0, 1));
        rx0 = fmaxf(rx0, __shfl_xor_sync(0xffffffffu, rx0, 2));
        rx1 = fmaxf(rx1, __shfl_xor_sync(0xffffffffu, rx1, 1));
        rx1 = fmaxf(rx1, __shfl_xor_sync(0xffffffffu, rx1, 2));

        const float mn0 = fmaxf(m0, rx0);
        const float mn1 = fmaxf(m1, rx1);
        const float a0 = ex2f(m0 - mn0);
        const float a1 = ex2f(m1 - mn1);
        m0 = mn0; m1 = mn1;
        l0 *= a0;  l1 *= a1;

#pragma unroll
        for (int nt = 0; nt < 8; nt++) {
            S[nt][0] = ex2f(S[nt][0] - m0);
            S[nt][1] = ex2f(S[nt][1] - m0);
            S[nt][2] = ex2f(S[nt][2] - m1);
            S[nt][3] = ex2f(S[nt][3] - m1);
            l0 += S[nt][0] + S[nt][1];
            l1 += S[nt][2] + S[nt][3];
            O[nt][0] *= a0; O[nt][1] *= a0;
            O[nt][2] *= a1; O[nt][3] *= a1;
        }

        // ---- O += P V (P split fp16 in registers, V single) ----
#pragma unroll
        for (int kt = 0; kt < 4; kt++) {
            uint32_t ah[4], al[4];
#pragma unroll
            for (int half = 0; half < 2; half++) {
                const float* sv = S[2 * kt + half];
                split2h(sv[0], sv[1], ah[half * 2 + 0], al[half * 2 + 0]);
                split2h(sv[2], sv[3], ah[half * 2 + 1], al[half * 2 + 1]);
            }

            const int kb = kt * 32 + qc * 4;
#pragma unroll
            for (int nt = 0; nt < 8; nt++) {
                const char* vp = smb + KTILE + (nt * 8 + qr) * ATS + kb;
                uint32_t vf[2];
                vf[0] = *(const uint32_t*)vp;
                vf[1] = *(const uint32_t*)(vp + 16);
                mma16816(O[nt], ah, vf);
                mma16816(O[nt], al, vf);
            }
        }
    }

    // ---- finalize: normalize + fused fp16 split store ----
    l0 += __shfl_xor_sync(0xffffffffu, l0, 1);
    l0 += __shfl_xor_sync(0xffffffffu, l0, 2);
    l1 += __shfl_xor_sync(0xffffffffu, l1, 1);
    l1 += __shfl_xor_sync(0xffffffffu, l1, 2);
    const float inv0 = 1.f / l0, inv1 = 1.f / l1;

    const int s = s0 + wid * 16 + qr;
#pragma unroll
    for (int nt = 0; nt < 8; nt++) {
        const int col = h * DK + nt * 8 + qc * 2;
        const size_t i0 = ((size_t)(b * SEQ + s)    ) * DMODEL + col;
        const size_t i1 = ((size_t)(b * SEQ + s + 8)) * DMODEL + col;
        uint32_t hp, lp;
        split2h(O[nt][0] * inv0, O[nt][1] * inv0, hp, lp);
        *(uint32_t*)(Chi + i0) = hp;
        *(uint32_t*)(Clo + i0) = lp;
        split2h(O[nt][2] * inv1, O[nt][3] * inv1, hp, lp);
        *(uint32_t*)(Chi + i1) = hp;
        *(uint32_t*)(Clo + i1) = lp;
    }
}

// ---------------- launch ---------------------------------------------------
extern "C" void kernel_launch(void* const* d_in, const int* in_sizes, int n_in,
                              void* d_out, int out_size)
{
    (void)in_sizes; (void)n_in; (void)out_size;
    const float* q    = (const float*)d_in[0];
    const float* k    = (const float*)d_in[1];
    const float* v    = (const float*)d_in[2];
    const float* wq_w = (const float*)d_in[4];
    const float* wq_b = (const float*)d_in[5];
    const float* wk_w = (const float*)d_in[6];
    const float* wk_b = (const float*)d_in[7];
    const float* wv_w = (const float*)d_in[8];
    const float* wv_b = (const float*)d_in[9];
    const float* wo_w = (const float*)d_in[10];
    const float* wo_b = (const float*)d_in[11];
    float* out = (float*)d_out;

    __half *qhi, *qlo, *khi, *klo, *vhi, *vlo, *chi, *clo;
    __half *wqh, *wkh, *wvh, *woh;
    __half *qsh, *qsl, *ksh, *vth;
    cudaGetSymbolAddress((void**)&qhi, g_qhi);  cudaGetSymbolAddress((void**)&qlo, g_qlo);
    cudaGetSymbolAddress((void**)&khi, g_khi);  cudaGetSymbolAddress((void**)&klo, g_klo);
    cudaGetSymbolAddress((void**)&vhi, g_vhi);  cudaGetSymbolAddress((void**)&vlo, g_vlo);
    cudaGetSymbolAddress((void**)&chi, g_chi);  cudaGetSymbolAddress((void**)&clo, g_clo);
    cudaGetSymbolAddress((void**)&wqh, g_wqh);  cudaGetSymbolAddress((void**)&wkh, g_wkh);
    cudaGetSymbolAddress((void**)&wvh, g_wvh);  cudaGetSymbolAddress((void**)&woh, g_woh);
    cudaGetSymbolAddress((void**)&qsh, g_qsh);  cudaGetSymbolAddress((void**)&qsl, g_qsl);
    cudaGetSymbolAddress((void**)&ksh, g_ksh);  cudaGetSymbolAddress((void**)&vth, g_vth);

    cudaFuncSetAttribute(qkv_gemm, cudaFuncAttributeMaxDynamicSharedMemorySize, GEMM_SMEM);
    cudaFuncSetAttribute(out_gemm, cudaFuncAttributeMaxDynamicSharedMemorySize, GEMM_SMEM);
    cudaFuncSetAttribute(flash_mma, cudaFuncAttributeMaxDynamicSharedMemorySize, FLASH_SMEM);

    const int nAct4 = MROWS * DMODEL / 4;
    const int nW4   = DMODEL * DMODEL / 4;

    {
        dim3 ga((nAct4 + 255) / 256, 3);
        split_fp16_multi<<<ga, 256>>>(
            (const float4*)q, (uint2*)qhi, (uint2*)qlo,
            (const float4*)k, (uint2*)khi, (uint2*)klo,
            (const float4*)v, (uint2*)vhi, (uint2*)vlo,
            nullptr, nullptr, nullptr, nAct4);
        dim3 gw((nW4 + 255) / 256, 4);
        split_fp16_multi<<<gw, 256>>>(
            (const float4*)wq_w, (uint2*)wqh, nullptr,
            (const float4*)wk_w, (uint2*)wkh, nullptr,
            (const float4*)wv_w, (uint2*)wvh, nullptr,
            (const float4*)wo_w, (uint2*)woh, nullptr, nW4);
    }

    const float qscale = 0.125f * 1.4426950408889634f;

    // fused Q/K/V projection: one launch, 768 CTAs
    dim3 qkvgrid(DMODEL / 128, MROWS / 128, 3);   // (8, 32, 3)
    qkv_gemm<<<qkvgrid, 256, GEMM_SMEM>>>(
        qhi, qlo, khi, klo, vhi, vlo,
        wqh, wkh, wvh, wq_b, wk_b, wv_b, qscale,
        qsh, qsl, ksh, vth);

    dim3 agrid(SEQ / 128, BH);                    // (16, 32)
    flash_mma<<<agrid, 256, FLASH_SMEM>>>(qsh, qsl, ksh, vth, chi, clo);

    dim3 ggrid(DMODEL / 128, MROWS / 128);        // (8, 32)
    out_gemm<<<ggrid, 256, GEMM_SMEM>>>(chi, clo, woh, wo_b, out);
}

// round 17
// speedup vs baseline: 2.1353x; 1.0117x over previous
#include <cuda_runtime.h>
#include <cuda_bf16.h>
#include <cuda_fp16.h>
#include <cstdint>

// Problem constants
#define DMODEL 1024
#define HEADS  16
#define DK     64
#define BATCH  2
#define SEQ    2048
#define MROWS  (BATCH * SEQ)          // 4096
#define BH     (BATCH * HEADS)        // 32

// ---------------- scratch (static device memory; no allocs) ----------------
__device__ __half g_qhi[MROWS * DMODEL], g_qlo[MROWS * DMODEL];
__device__ __half g_khi[MROWS * DMODEL], g_klo[MROWS * DMODEL];
__device__ __half g_vhi[MROWS * DMODEL], g_vlo[MROWS * DMODEL];
__device__ __half g_chi[MROWS * DMODEL], g_clo[MROWS * DMODEL];
__device__ __half g_wqh[DMODEL * DMODEL];
__device__ __half g_wkh[DMODEL * DMODEL];
__device__ __half g_wvh[DMODEL * DMODEL];
__device__ __half g_woh[DMODEL * DMODEL];
__device__ __half g_qsh[BH * SEQ * DK], g_qsl[BH * SEQ * DK]; // Q split [bh][s][dk]
__device__ __half g_ksh[BH * SEQ * DK];                        // K single [bh][s][dk]
__device__ __half g_vth[BH * DK * SEQ];                        // V single [bh][dk][s]

// ---------------- helpers ---------------------------------------------------
__device__ __forceinline__ void mma16816(float* c, const uint32_t* a, const uint32_t* b) {
    asm volatile(
        "mma.sync.aligned.m16n8k16.row.col.f32.f16.f16.f32 "
        "{%0,%1,%2,%3}, {%4,%5,%6,%7}, {%8,%9}, {%0,%1,%2,%3};"
        : "+f"(c[0]), "+f"(c[1]), "+f"(c[2]), "+f"(c[3])
        : "r"(a[0]), "r"(a[1]), "r"(a[2]), "r"(a[3]), "r"(b[0]), "r"(b[1]));
}
__device__ __forceinline__ void ldsm4(uint32_t* r, uint32_t addr) {
    asm volatile("ldmatrix.sync.aligned.m8n8.x4.shared.b16 {%0,%1,%2,%3}, [%4];"
        : "=r"(r[0]), "=r"(r[1]), "=r"(r[2]), "=r"(r[3]) : "r"(addr));
}
__device__ __forceinline__ uint32_t smem_u32(const void* p) {
    uint32_t a;
    asm("{ .reg .u64 t; cvta.to.shared.u64 t, %1; cvt.u32.u64 %0, t; }"
        : "=r"(a) : "l"(p));
    return a;
}
__device__ __forceinline__ void cpa16(uint32_t dst, const void* src) {
    asm volatile("cp.async.cg.shared.global [%0], [%1], 16;" :: "r"(dst), "l"(src));
}
__device__ __forceinline__ void cpa_commit() {
    asm volatile("cp.async.commit_group;" ::: "memory");
}
template <int N>
__device__ __forceinline__ void cpa_wait() {
    asm volatile("cp.async.wait_group %0;" :: "n"(N) : "memory");
}
__device__ __forceinline__ float ex2f(float x) {
    float y; asm("ex2.approx.ftz.f32 %0, %1;" : "=f"(y) : "f"(x)); return y;
}
__device__ __forceinline__ uint32_t packh2(__half a, __half b) {
    __half2 t = __halves2half2(a, b);
    return *reinterpret_cast<uint32_t*>(&t);
}
__device__ __forceinline__ void split2h(float a, float b, uint32_t& hi, uint32_t& lo) {
    __half ha = __float2half_rn(a);
    __half hb = __float2half_rn(b);
    hi = packh2(ha, hb);
    lo = packh2(__float2half_rn(a - __half2float(ha)),
                __float2half_rn(b - __half2float(hb)));
}

// ---------------- fp32 -> fp16 split / convert (batched up to 4 tensors) ---
__global__ __launch_bounds__(256) void split_fp16_multi(
    const float4* __restrict__ x0, uint2* __restrict__ h0, uint2* __restrict__ l0,
    const float4* __restrict__ x1, uint2* __restrict__ h1, uint2* __restrict__ l1,
    const float4* __restrict__ x2, uint2* __restrict__ h2, uint2* __restrict__ l2,
    const float4* __restrict__ x3, uint2* __restrict__ h3, uint2* __restrict__ l3,
    int n4)
{
    const int sel = blockIdx.y;
    const float4* x = (sel == 0) ? x0 : (sel == 1) ? x1 : (sel == 2) ? x2 : x3;
    uint2* hi = (sel == 0) ? h0 : (sel == 1) ? h1 : (sel == 2) ? h2 : h3;
    uint2* lo = (sel == 0) ? l0 : (sel == 1) ? l1 : (sel == 2) ? l2 : l3;
    if (x == nullptr) return;

    int i = blockIdx.x * blockDim.x + threadIdx.x;
    if (i >= n4) return;
    float4 v = x[i];
    if (lo != nullptr) {
        uint32_t h01, l01, h23, l23;
        split2h(v.x, v.y, h01, l01);
        split2h(v.z, v.w, h23, l23);
        hi[i] = make_uint2(h01, h23);
        lo[i] = make_uint2(l01, l23);
    } else {
        hi[i] = make_uint2(packh2(__float2half_rn(v.x), __float2half_rn(v.y)),
                           packh2(__float2half_rn(v.z), __float2half_rn(v.w)));
    }
}

// ---------------- fp16 2-product GEMM core (R15-proven mainloop) -----------
#define TSTRIDE   80
#define TILE_B    (128 * TSTRIDE)      // 10240
#define GBUF      (3 * TILE_B)         // Ah|Al|Bh = 30720
#define GEMM_SMEM (3 * GBUF)           // 92160 -> 2 CTAs/SM
#define NCHUNK    32

struct GemmCtx {
    int tid, wid, lane, wm, wn, qr, qc, lrow, lbyt, row0, col0;
    uint32_t sb;
};

__device__ __forceinline__ void gemm_mainloop(
    const GemmCtx& g,
    const __half* __restrict__ Ah, const __half* __restrict__ Al,
    const __half* __restrict__ Bh, float acc[2][8][4])
{
#pragma unroll
    for (int a = 0; a < 2; a++)
#pragma unroll
        for (int b = 0; b < 8; b++)
#pragma unroll
            for (int c = 0; c < 4; c++) acc[a][b][c] = 0.f;

    auto cpa_chunk = [&](int c, int buf) {
        const uint32_t db = g.sb + buf * GBUF;
#pragma unroll
        for (int i = 0; i < 6; i++) {
            const int u   = g.tid + i * 256;
            const int arr = u >> 9;            // 0=Ah 1=Al 2=Bh
            const int r   = (u & 511) >> 2;
            const int ch  = u & 3;
            const __half* src = (arr == 0) ? Ah : (arr == 1) ? Al : Bh;
            const int grow = ((arr < 2) ? g.row0 : g.col0) + r;
            cpa16(db + arr * TILE_B + r * TSTRIDE + ch * 16,
                  src + (size_t)grow * DMODEL + c * 32 + ch * 8);
        }
        cpa_commit();
    };

    cpa_chunk(0, 0);
    cpa_chunk(1, 1);

#pragma unroll 1
    for (int c = 0; c < NCHUNK; c++) {
        if (c == NCHUNK - 1) cpa_wait<0>(); else cpa_wait<1>();
        __syncthreads();
        if (c + 2 < NCHUNK) cpa_chunk(c + 2, (c + 2) % 3);

        const uint32_t bb = g.sb + (c % 3) * GBUF;
#pragma unroll
        for (int ks = 0; ks < 2; ks++) {
            const int kb = ks * 32 + g.lbyt;

            uint32_t bf[8][2];
#pragma unroll
            for (int half = 0; half < 4; half++) {
                const uint32_t addr = bb + 2 * TILE_B
                    + (g.wn * 64 + half * 16 + g.lrow) * TSTRIDE + kb;
                uint32_t th[4];
                ldsm4(th, addr);
                bf[half * 2 + 0][0] = th[0]; bf[half * 2 + 1][0] = th[1];
                bf[half * 2 + 0][1] = th[2]; bf[half * 2 + 1][1] = th[3];
            }
#pragma unroll
            for (int mt = 0; mt < 2; mt++) {
                const uint32_t addr = bb + (g.wm * 32 + mt * 16 + g.lrow) * TSTRIDE + kb;
                uint32_t ah[4], al[4];
                ldsm4(ah, addr);
                ldsm4(al, addr + TILE_B);
#pragma unroll
                for (int nt = 0; nt < 8; nt++) {
                    mma16816(acc[mt][nt], ah, bf[nt]);
                    mma16816(acc[mt][nt], al, bf[nt]);
                }
            }
        }
    }
}

__device__ __forceinline__ GemmCtx make_ctx(uint32_t sb, int row0, int col0) {
    GemmCtx g;
    g.tid = threadIdx.x;
    g.wid = g.tid >> 5; g.lane = g.tid & 31;
    g.wm = g.wid & 3;   g.wn = g.wid >> 2;
    g.qr = g.lane >> 2; g.qc = g.lane & 3;
    g.lrow = (g.lane & 7) + ((g.lane >> 3) & 1) * 8;
    g.lbyt = (g.lane >> 4) * 16;
    g.row0 = row0; g.col0 = col0; g.sb = sb;
    return g;
}

// ---- fused QKV projection: blockIdx.z selects {Q, K, V} -------------------
__global__ __launch_bounds__(256, 2) void qkv_gemm(
    const __half* __restrict__ Aqh, const __half* __restrict__ Aql,
    const __half* __restrict__ Akh, const __half* __restrict__ Akl,
    const __half* __restrict__ Avh, const __half* __restrict__ Avl,
    const __half* __restrict__ Wq, const __half* __restrict__ Wk,
    const __half* __restrict__ Wv,
    const float* __restrict__ bq, const float* __restrict__ bk,
    const float* __restrict__ bv, float qscale,
    __half* __restrict__ Qh, __half* __restrict__ Ql,
    __half* __restrict__ Kh, __half* __restrict__ Vt)
{
    extern __shared__ __align__(16) char smem_raw[];
    const int z = blockIdx.z;
    const GemmCtx g = make_ctx(smem_u32(smem_raw),
                               blockIdx.y * 128, blockIdx.x * 128);

    const __half* Ah = (z == 0) ? Aqh : (z == 1) ? Akh : Avh;
    const __half* Al = (z == 0) ? Aql : (z == 1) ? Akl : Avl;
    const __half* Bh = (z == 0) ? Wq  : (z == 1) ? Wk  : Wv;
    const float* bias = (z == 0) ? bq : (z == 1) ? bk : bv;
    const float scale = (z == 0) ? qscale : 1.0f;

    float acc[2][8][4];
    gemm_mainloop(g, Ah, Al, Bh, acc);

#pragma unroll
    for (int mt = 0; mt < 2; mt++) {
#pragma unroll
        for (int nt = 0; nt < 8; nt++) {
            const int col = g.col0 + g.wn * 64 + nt * 8 + g.qc * 2;
            float2 bv2 = *(const float2*)&bias[col];
#pragma unroll
            for (int h = 0; h < 2; h++) {
                const int m = g.row0 + g.wm * 32 + mt * 16 + g.qr + h * 8;
                float v0 = (acc[mt][nt][h * 2 + 0] + bv2.x) * scale;
                float v1 = (acc[mt][nt][h * 2 + 1] + bv2.y) * scale;
                const int b  = m >> 11, s = m & (SEQ - 1);
                const int hh = col >> 6, dk = col & 63;
                if (z == 0) {              // Q: split fp16
                    uint32_t hp, lp;
                    split2h(v0, v1, hp, lp);
                    const size_t idx = ((size_t)(b * HEADS + hh) * SEQ + s) * DK + dk;
                    *(uint32_t*)(Qh + idx) = hp;
                    *(uint32_t*)(Ql + idx) = lp;
                } else if (z == 1) {       // K: single fp16
                    const size_t idx = ((size_t)(b * HEADS + hh) * SEQ + s) * DK + dk;
                    *(uint32_t*)(Kh + idx) =
                        packh2(__float2half_rn(v0), __float2half_rn(v1));
                } else {                   // V: single fp16, [bh][dk][s]
                    const size_t base = ((size_t)(b * HEADS + hh) * DK + dk) * SEQ + s;
                    Vt[base]       = __float2half_rn(v0);
                    Vt[base + SEQ] = __float2half_rn(v1);
                }
            }
        }
    }
}

// ---- output projection: ctx(split) @ Wo + bias -> fp32 out ---------------
__global__ __launch_bounds__(256, 2) void out_gemm(
    const __half* __restrict__ Ah, const __half* __restrict__ Al,
    const __half* __restrict__ Bh,
    const float* __restrict__ bias, float* __restrict__ Yf)
{
    extern __shared__ __align__(16) char smem_raw[];
    const GemmCtx g = make_ctx(smem_u32(smem_raw),
                               blockIdx.y * 128, blockIdx.x * 128);

    float acc[2][8][4];
    gemm_mainloop(g, Ah, Al, Bh, acc);

#pragma unroll
    for (int mt = 0; mt < 2; mt++) {
#pragma unroll
        for (int nt = 0; nt < 8; nt++) {
            const int col = g.col0 + g.wn * 64 + nt * 8 + g.qc * 2;
            float2 bv2 = *(const float2*)&bias[col];
#pragma unroll
            for (int h = 0; h < 2; h++) {
                const int m = g.row0 + g.wm * 32 + mt * 16 + g.qr + h * 8;
                float2 r;
                r.x = acc[mt][nt][h * 2 + 0] + bv2.x;
                r.y = acc[mt][nt][h * 2 + 1] + bv2.y;
                *(float2*)(Yf + (size_t)m * DMODEL + col) = r;
            }
        }
    }
}

// ---------------- fp16 2-product flash attention ----------------------------
// R16 kernel + outer loop over 2 sequential Q tiles -> grid (8, 32) = 256
// CTAs = single wave at occ 2 (kills the 1.73-wave tail).
#define ATS    144
#define KTILE  (64 * ATS)              // 9216
#define QTILE  (128 * ATS)             // 18432
#define FBUF   (2 * KTILE)             // Kh|Vth = 18432
#define FLASH_SMEM (3 * FBUF)          // 55296 -> 2 CTAs/SM
#define NT     (SEQ / 64)              // 32

__global__ __launch_bounds__(256, 2) void flash_mma(
    const __half* __restrict__ Qh, const __half* __restrict__ Ql,
    const __half* __restrict__ Kh, const __half* __restrict__ Vth,
    __half* __restrict__ Chi, __half* __restrict__ Clo)
{
    extern __shared__ __align__(16) char sm[];
    const uint32_t sbf = smem_u32(sm);

    const int tid = threadIdx.x, wid = tid >> 5, lane = tid & 31;
    const int qr = lane >> 2, qc = lane & 3;
    const int bh = blockIdx.y;
    const int b  = bh >> 4, h = bh & 15;

#pragma unroll 1
    for (int qt = 0; qt < 2; qt++) {
        const int s0 = blockIdx.x * 256 + qt * 128;

        // ---- stage Q tile (qh at 0, ql at QTILE), extract A-fragments ----
        __syncthreads();                // prior tile fully done with smem
#pragma unroll
        for (int i = 0; i < 8; i++) {
            int u = tid + i * 256;      // 0..2047
            int arr = u >> 10;          // 0=hi 1=lo
            int idx = u & 1023, r = idx >> 3, ch = idx & 7;
            const __half* src = arr ? Ql : Qh;
            *(float4*)(sm + arr * QTILE + r * ATS + ch * 16) =
                *(const float4*)(src + ((size_t)bh * SEQ + s0 + r) * DK + ch * 8);
        }
        __syncthreads();
        uint32_t qfh[4][4], qfl[4][4];
        {
            const char* base = sm + (wid * 16 + qr) * ATS;
#pragma unroll
            for (int kt = 0; kt < 4; kt++) {
                const int off = kt * 32 + qc * 4;
                qfh[kt][0] = *(const uint32_t*)(base + off);
                qfh[kt][1] = *(const uint32_t*)(base + 8 * ATS + off);
                qfh[kt][2] = *(const uint32_t*)(base + off + 16);
                qfh[kt][3] = *(const uint32_t*)(base + 8 * ATS + off + 16);
                qfl[kt][0] = *(const uint32_t*)(base + QTILE + off);
                qfl[kt][1] = *(const uint32_t*)(base + QTILE + 8 * ATS + off);
                qfl[kt][2] = *(const uint32_t*)(base + QTILE + off + 16);
                qfl[kt][3] = *(const uint32_t*)(base + QTILE + 8 * ATS + off + 16);
            }
        }
        __syncthreads();                // Q fully consumed before buffer reuse

        float O[8][4];
#pragma unroll
        for (int nt = 0; nt < 8; nt++)
#pragma unroll
            for (int c = 0; c < 4; c++) O[nt][c] = 0.f;
        float m0 = -1e30f, m1 = -1e30f, l0 = 0.f, l1 = 0.f;

        auto cpaKV = [&](int t, int buf) {
            const uint32_t db = sbf + buf * FBUF;
            const int j0 = t * 64;
#pragma unroll
            for (int i = 0; i < 4; i++) {
                int u = tid + i * 256;
                int arr = u >> 9;       // 0=Kh 1=Vth
                int idx = u & 511, r = idx >> 3, ch = idx & 7;
                const __half* src = arr ? Vth : Kh;
                size_t g = (arr == 0)
                    ? (((size_t)bh * SEQ + j0 + r) * DK + ch * 8)
                    : (((size_t)bh * DK + r) * SEQ + j0 + ch * 8);
                cpa16(db + arr * KTILE + r * ATS + ch * 16, src + g);
            }
            cpa_commit();
        };

        cpaKV(0, 0);
        cpaKV(1, 1);

#pragma unroll 1
        for (int t = 0; t < NT; t++) {
            if (t == NT - 1) cpa_wait<0>(); else cpa_wait<1>();
            __syncthreads();
            if (t + 2 < NT) cpaKV(t + 2, (t + 2) % 3);
            const char* smb = sm + (t % 3) * FBUF;

            // ---- S = Q K^T (2-product fp16), base-2 domain ----
            float S[8][4];
#pragma unroll
            for (int nt = 0; nt < 8; nt++)
#pragma unroll
                for (int c = 0; c < 4; c++) S[nt][c] = 0.f;

#pragma unroll
            for (int kt = 0; kt < 4; kt++) {
                const int kb = kt * 32 + qc * 4;
#pragma unroll
                for (int nt = 0; nt < 8; nt++) {
                    const char* kp = smb + (nt * 8 + qr) * ATS + kb;
                    uint32_t kf[2];
                    kf[0] = *(const uint32_t*)kp;
                    kf[1] = *(const uint32_t*)(kp + 16);
                    mma16816(S[nt], qfh[kt], kf);
                    mma16816(S[nt], qfl[kt], kf);
                }
            }

            // ---- online softmax (base 2) ----
            float rx0 = -1e30f, rx1 = -1e30f;
#pragma unroll
            for (int nt = 0; nt < 8; nt++) {
                rx0 = fmaxf(rx0, fmaxf(S[nt][0], S[nt][1]));
                rx1 = fmaxf(rx1, fmaxf(S[nt][2], S[nt][3]));
            }
            rx0 = fmaxf(rx0, __shfl_xor_sync(0xffffffffu, rx0, 1));
            rx0 = fmaxf(rx0, __shfl_xor_sync(0xffffffffu, rx0, 2));
            rx1 = fmaxf(rx1, __shfl_xor_sync(0xffffffffu, rx1, 1));
            rx1 = fmaxf(rx1, __shfl_xor_sync(0xffffffffu, rx1, 2));

            const float mn0 = fmaxf(m0, rx0);
            const float mn1 = fmaxf(m1, rx1);
            const float a0 = ex2f(m0 - mn0);
            const float a1 = ex2f(m1 - mn1);
            m0 = mn0; m1 = mn1;
            l0 *= a0;  l1 *= a1;

#pragma unroll
            for (int nt = 0; nt < 8; nt++) {
                S[nt][0] = ex2f(S[nt][0] - m0);
                S[nt][1] = ex2f(S[nt][1] - m0);
                S[nt][2] = ex2f(S[nt][2] - m1);
                S[nt][3] = ex2f(S[nt][3] - m1);
                l0 += S[nt][0] + S[nt][1];
                l1 += S[nt][2] + S[nt][3];
                O[nt][0] *= a0; O[nt][1] *= a0;
                O[nt][2] *= a1; O[nt][3] *= a1;
            }

            // ---- O += P V (P split fp16 in registers, V single) ----
#pragma unroll
            for (int kt = 0; kt < 4; kt++) {
                uint32_t ah[4], al[4];
#pragma unroll
                for (int half = 0; half < 2; half++) {
                    const float* sv = S[2 * kt + half];
                    split2h(sv[0], sv[1], ah[half * 2 + 0], al[half * 2 + 0]);
                    split2h(sv[2], sv[3], ah[half * 2 + 1], al[half * 2 + 1]);
                }

                const int kb = kt * 32 + qc * 4;
#pragma unroll
                for (int nt = 0; nt < 8; nt++) {
                    const char* vp = smb + KTILE + (nt * 8 + qr) * ATS + kb;
                    uint32_t vf[2];
                    vf[0] = *(const uint32_t*)vp;
                    vf[1] = *(const uint32_t*)(vp + 16);
                    mma16816(O[nt], ah, vf);
                    mma16816(O[nt], al, vf);
                }
            }
        }

        // ---- finalize: normalize + fused fp16 split store ----
        l0 += __shfl_xor_sync(0xffffffffu, l0, 1);
        l0 += __shfl_xor_sync(0xffffffffu, l0, 2);
        l1 += __shfl_xor_sync(0xffffffffu, l1, 1);
        l1 += __shfl_xor_sync(0xffffffffu, l1, 2);
        const float inv0 = 1.f / l0, inv1 = 1.f / l1;

        const int s = s0 + wid * 16 + qr;
#pragma unroll
        for (int nt = 0; nt < 8; nt++) {
            const int col = h * DK + nt * 8 + qc * 2;
            const size_t i0 = ((size_t)(b * SEQ + s)    ) * DMODEL + col;
            const size_t i1 = ((size_t)(b * SEQ + s + 8)) * DMODEL + col;
            uint32_t hp, lp;
            split2h(O[nt][0] * inv0, O[nt][1] * inv0, hp, lp);
            *(uint32_t*)(Chi + i0) = hp;
            *(uint32_t*)(Clo + i0) = lp;
            split2h(O[nt][2] * inv1, O[nt][3] * inv1, hp, lp);
            *(uint32_t*)(Chi + i1) = hp;
            *(uint32_t*)(Clo + i1) = lp;
        }
    }
}

// ---------------- launch ---------------------------------------------------
extern "C" void kernel_launch(void* const* d_in, const int* in_sizes, int n_in,
                              void* d_out, int out_size)
{
    (void)in_sizes; (void)n_in; (void)out_size;
    const float* q    = (const float*)d_in[0];
    const float* k    = (const float*)d_in[1];
    const float* v    = (const float*)d_in[2];
    const float* wq_w = (const float*)d_in[4];
    const float* wq_b = (const float*)d_in[5];
    const float* wk_w = (const float*)d_in[6];
    const float* wk_b = (const float*)d_in[7];
    const float* wv_w = (const float*)d_in[8];
    const float* wv_b = (const float*)d_in[9];
    const float* wo_w = (const float*)d_in[10];
    const float* wo_b = (const float*)d_in[11];
    float* out = (float*)d_out;

    __half *qhi, *qlo, *khi, *klo, *vhi, *vlo, *chi, *clo;
    __half *wqh, *wkh, *wvh, *woh;
    __half *qsh, *qsl, *ksh, *vth;
    cudaGetSymbolAddress((void**)&qhi, g_qhi);  cudaGetSymbolAddress((void**)&qlo, g_qlo);
    cudaGetSymbolAddress((void**)&khi, g_khi);  cudaGetSymbolAddress((void**)&klo, g_klo);
    cudaGetSymbolAddress((void**)&vhi, g_vhi);  cudaGetSymbolAddress((void**)&vlo, g_vlo);
    cudaGetSymbolAddress((void**)&chi, g_chi);  cudaGetSymbolAddress((void**)&clo, g_clo);
    cudaGetSymbolAddress((void**)&wqh, g_wqh);  cudaGetSymbolAddress((void**)&wkh, g_wkh);
    cudaGetSymbolAddress((void**)&wvh, g_wvh);  cudaGetSymbolAddress((void**)&woh, g_woh);
    cudaGetSymbolAddress((void**)&qsh, g_qsh);  cudaGetSymbolAddress((void**)&qsl, g_qsl);
    cudaGetSymbolAddress((void**)&ksh, g_ksh);  cudaGetSymbolAddress((void**)&vth, g_vth);

    cudaFuncSetAttribute(qkv_gemm, cudaFuncAttributeMaxDynamicSharedMemorySize, GEMM_SMEM);
    cudaFuncSetAttribute(out_gemm, cudaFuncAttributeMaxDynamicSharedMemorySize, GEMM_SMEM);
    cudaFuncSetAttribute(flash_mma, cudaFuncAttributeMaxDynamicSharedMemorySize, FLASH_SMEM);

    const int nAct4 = MROWS * DMODEL / 4;
    const int nW4   = DMODEL * DMODEL / 4;

    {
        dim3 ga((nAct4 + 255) / 256, 3);
        split_fp16_multi<<<ga, 256>>>(
            (const float4*)q, (uint2*)qhi, (uint2*)qlo,
            (const float4*)k, (uint2*)khi, (uint2*)klo,
            (const float4*)v, (uint2*)vhi, (uint2*)vlo,
            nullptr, nullptr, nullptr, nAct4);
        dim3 gw((nW4 + 255) / 256, 4);
        split_fp16_multi<<<gw, 256>>>(
            (const float4*)wq_w, (uint2*)wqh, nullptr,
            (const float4*)wk_w, (uint2*)wkh, nullptr,
            (const float4*)wv_w, (uint2*)wvh, nullptr,
            (const float4*)wo_w, (uint2*)woh, nullptr, nW4);
    }

    const float qscale = 0.125f * 1.4426950408889634f;

    // fused Q/K/V projection: one launch, 768 CTAs
    dim3 qkvgrid(DMODEL / 128, MROWS / 128, 3);   // (8, 32, 3)
    qkv_gemm<<<qkvgrid, 256, GEMM_SMEM>>>(
        qhi, qlo, khi, klo, vhi, vlo,
        wqh, wkh, wvh, wq_b, wk_b, wv_b, qscale,
        qsh, qsl, ksh, vth);

    // flash: 2 sequential Q tiles per CTA -> 256 CTAs = one wave @ occ 2
    dim3 agrid(SEQ / 256, BH);                    // (8, 32)
    flash_mma<<<agrid, 256, FLASH_SMEM>>>(qsh, qsl, ksh, vth, chi, clo);

    dim3 ggrid(DMODEL / 128, MROWS / 128);        // (8, 32)
    out_gemm<<<ggrid, 256, GEMM_SMEM>>>(chi, clo, woh, wo_b, out);
}